// round 12
// baseline (speedup 1.0000x reference)
#include <cuda_runtime.h>
#include <cuda_bf16.h>
#include <math.h>
#include <stdint.h>

#define Bq 2
#define Sq 2048
#define Dq 1024
#define Hq 16
#define DHq 64
#define Mq (Bq*Sq)
#define NELEM (Mq*Dq)
#define WN (Dq*Dq)
#define OUT_OFF ((size_t)Mq*Dq)

typedef __nv_bfloat16 bf16;
typedef __nv_bfloat162 bf162;

// SW128 swizzle (byte offsets)
#define SWZ(x) ((x) ^ ((((uint32_t)(x))>>3)&0x70))

// ---------------- global scratch (no allocs allowed) ----------------
__device__ __align__(16) bf16 g_pah[3][NELEM], g_pal[3][NELEM];   // inputs Q,K,V
__device__ __align__(16) bf16 g_pwh[4][WN],    g_pwl[4][WN];      // weights
__device__ __align__(16) bf16 g_pch[NELEM],    g_pcl[NELEM];      // ctx (tile-major)
__device__ __align__(16) bf16 g_qh[NELEM], g_ql[NELEM];           // q tile-major
__device__ __align__(16) bf16 g_kh[NELEM], g_kl[NELEM];           // k tile-major
__device__ __align__(16) bf16 g_vh[NELEM], g_vl[NELEM];           // v row-major
__device__ float g_y[NELEM];
__device__ float g_psum[(size_t)Bq*Hq*16*Sq];

// ---------------- helpers ----------------
__device__ __forceinline__ uint32_t s2u(const void* p){ return (uint32_t)__cvta_generic_to_shared(p); }
__device__ __forceinline__ void cpa16(uint32_t s, const void* g){
    asm volatile("cp.async.cg.shared.global [%0], [%1], 16;\n" :: "r"(s), "l"(g));
}
__device__ __forceinline__ void cpcommit(){ asm volatile("cp.async.commit_group;\n" ::: "memory"); }
__device__ __forceinline__ void ldm4(uint32_t a, uint32_t&r0,uint32_t&r1,uint32_t&r2,uint32_t&r3){
    asm volatile("ldmatrix.sync.aligned.m8n8.x4.shared.b16 {%0,%1,%2,%3}, [%4];\n"
        : "=r"(r0),"=r"(r1),"=r"(r2),"=r"(r3) : "r"(a));
}
__device__ __forceinline__ void ldm4t(uint32_t a, uint32_t&r0,uint32_t&r1,uint32_t&r2,uint32_t&r3){
    asm volatile("ldmatrix.sync.aligned.m8n8.x4.trans.shared.b16 {%0,%1,%2,%3}, [%4];\n"
        : "=r"(r0),"=r"(r1),"=r"(r2),"=r"(r3) : "r"(a));
}
__device__ __forceinline__ void mma16(float* c, uint32_t a0,uint32_t a1,uint32_t a2,uint32_t a3,
                                      uint32_t b0,uint32_t b1){
    asm volatile("mma.sync.aligned.m16n8k16.row.col.f32.bf16.bf16.f32 "
        "{%0,%1,%2,%3}, {%4,%5,%6,%7}, {%8,%9}, {%0,%1,%2,%3};\n"
        : "+f"(c[0]),"+f"(c[1]),"+f"(c[2]),"+f"(c[3])
        : "r"(a0),"r"(a1),"r"(a2),"r"(a3),"r"(b0),"r"(b1));
}
__device__ __forceinline__ void split2(float x, bf16& h, bf16& l){
    h = __float2bfloat16(x);
    l = __float2bfloat16(x - __bfloat162float(h));
}

// ---- bulk TMA + mbarrier ----
__device__ __forceinline__ void bulk_ld(uint32_t dst, const void* src, uint32_t bytes, uint32_t mbar){
    asm volatile("cp.async.bulk.shared::cta.global.mbarrier::complete_tx::bytes [%0], [%1], %2, [%3];\n"
        :: "r"(dst), "l"(src), "r"(bytes), "r"(mbar) : "memory");
}
__device__ __forceinline__ void mbar_init(uint32_t mbar, uint32_t cnt){
    asm volatile("mbarrier.init.shared.b64 [%0], %1;\n" :: "r"(mbar), "r"(cnt) : "memory");
}
__device__ __forceinline__ void mbar_expect(uint32_t mbar, uint32_t tx){
    asm volatile("mbarrier.arrive.expect_tx.shared.b64 _, [%0], %1;\n" :: "r"(mbar), "r"(tx) : "memory");
}
__device__ __forceinline__ void mbar_wait(uint32_t mbar, uint32_t parity){
    asm volatile("{\n\t.reg .pred P;\n\t"
        "W%=:\n\t"
        "mbarrier.try_wait.parity.acquire.cta.shared::cta.b64 P, [%0], %1, 0x989680;\n\t"
        "@!P bra W%=;\n\t}\n"
        :: "r"(mbar), "r"(parity) : "memory");
}

// ---------------- split all 7 f32 matrices in ONE launch ----------------
__global__ void split_all(const float* __restrict__ Q, const float* __restrict__ K,
                          const float* __restrict__ V, const float* __restrict__ W0,
                          const float* __restrict__ W1, const float* __restrict__ W2,
                          const float* __restrict__ W3)
{
    const int y = blockIdx.y;
    const float* src;
    bf16 *th, *tl;
    int n4;
    if (y < 3){
        src = (y==0) ? Q : (y==1) ? K : V;
        th = g_pah[y]; tl = g_pal[y]; n4 = NELEM/4;
    } else {
        const int w = y - 3;
        src = (w==0) ? W0 : (w==1) ? W1 : (w==2) ? W2 : W3;
        th = g_pwh[w]; tl = g_pwl[w]; n4 = WN/4;
    }
    const int i = blockIdx.x*blockDim.x + threadIdx.x;
    if (i >= n4) return;
    const int r = i >> 8, c4 = (i & 255) << 2;
    float4 v = reinterpret_cast<const float4*>(src)[i];
    bf16 h0,l0,h1,l1,h2,l2,h3,l3;
    split2(v.x,h0,l0); split2(v.y,h1,l1); split2(v.z,h2,l2); split2(v.w,h3,l3);
    const size_t tile = (size_t)((r>>7)*16 + (c4>>6)) * 16384;
    const uint32_t off = SWZ(((r&127)<<7) + ((c4&63)<<1));
    char* dh = (char*)th + tile + off;
    char* dl = (char*)tl + tile + off;
    *reinterpret_cast<bf162*>(dh)   = __halves2bfloat162(h0,h1);
    *reinterpret_cast<bf162*>(dh+4) = __halves2bfloat162(h2,h3);
    *reinterpret_cast<bf162*>(dl)   = __halves2bfloat162(l0,l1);
    *reinterpret_cast<bf162*>(dl+4) = __halves2bfloat162(l2,l3);
}

// ============================================================
// Projection GEMM (NT, mma.sync, bulk-TMA staged) — unchanged
// ============================================================
#define PR_STAGE 65536
#define PR_SMEM  (128 + 2*PR_STAGE)

__global__ __launch_bounds__(256,1) void proj_kernel(
    const bf16* __restrict__ Ahg0, const bf16* __restrict__ Alg0,
    const bf16* __restrict__ Bhg0, const bf16* __restrict__ Blg0,
    const float* __restrict__ bias0, const float* __restrict__ bias1,
    const float* __restrict__ bias2, const float* __restrict__ resid,
    float* __restrict__ outf, int qkv)
{
    extern __shared__ __align__(128) char sm_[];
    const int tid = threadIdx.x, lane = tid&31, warp = tid>>5;
    const int n0 = blockIdx.x, m0 = blockIdx.y, z = blockIdx.z;
    const bf16* Ahg = Ahg0 + (size_t)z*NELEM;
    const bf16* Alg = Alg0 + (size_t)z*NELEM;
    const bf16* Bhg = Bhg0 + (size_t)z*WN;
    const bf16* Blg = Blg0 + (size_t)z*WN;
    const float* bias = (z==0) ? bias0 : (z==1) ? bias1 : bias2;
    const uint32_t sb = s2u(sm_);
    const uint32_t dat = sb + 128;

    if (tid == 0){
        mbar_init(sb+0, 1);
        mbar_init(sb+8, 1);
#pragma unroll
        for (int p = 0; p < 2; p++){
            const uint32_t mb = sb + p*8;
            const uint32_t buf = dat + p*PR_STAGE;
            mbar_expect(mb, PR_STAGE);
            bulk_ld(buf,        (const char*)Ahg + (size_t)(m0*16+p)*16384, 16384, mb);
            bulk_ld(buf+16384,  (const char*)Alg + (size_t)(m0*16+p)*16384, 16384, mb);
            bulk_ld(buf+32768,  (const char*)Bhg + (size_t)(n0*16+p)*16384, 16384, mb);
            bulk_ld(buf+49152,  (const char*)Blg + (size_t)(n0*16+p)*16384, 16384, mb);
        }
    }
    __syncthreads();

    const int wm = (warp>>2)*64, wn = (warp&3)*32;
    float acc[4][4][4] = {};

    for (int kt = 0; kt < 16; kt++){
        const int b = kt & 1;
        mbar_wait(sb + b*8, (kt>>1)&1);
        const uint32_t buf = dat + b*PR_STAGE;
#pragma unroll
        for (int ks = 0; ks < 4; ks++){
            uint32_t bhf[4][2], blf[4][2];
#pragma unroll
            for (int p = 0; p < 2; p++){
                const uint32_t roff = (uint32_t)(wn + p*16 + (lane&7) + ((lane>>4)&1)*8)*128
                                      + ks*32 + ((lane>>3)&1)*16;
                ldm4(buf + 32768 + SWZ(roff), bhf[2*p][0], bhf[2*p][1], bhf[2*p+1][0], bhf[2*p+1][1]);
                ldm4(buf + 49152 + SWZ(roff), blf[2*p][0], blf[2*p][1], blf[2*p+1][0], blf[2*p+1][1]);
            }
#pragma unroll
            for (int mi = 0; mi < 4; mi++){
                const uint32_t roff = (uint32_t)(wm + mi*16 + (lane&15))*128
                                      + ks*32 + ((lane>>4)&1)*16;
                uint32_t a0,a1,a2,a3, l0,l1,l2,l3;
                ldm4(buf +         SWZ(roff), a0,a1,a2,a3);
                ldm4(buf + 16384 + SWZ(roff), l0,l1,l2,l3);
#pragma unroll
                for (int ni = 0; ni < 4; ni++){
                    mma16(acc[mi][ni], a0,a1,a2,a3, bhf[ni][0], bhf[ni][1]);
                    mma16(acc[mi][ni], a0,a1,a2,a3, blf[ni][0], blf[ni][1]);
                    mma16(acc[mi][ni], l0,l1,l2,l3, bhf[ni][0], bhf[ni][1]);
                }
            }
        }
        __syncthreads();
        if (tid == 0 && kt+2 < 16){
            const uint32_t mb = sb + b*8;
            mbar_expect(mb, PR_STAGE);
            bulk_ld(buf,        (const char*)Ahg + (size_t)(m0*16+kt+2)*16384, 16384, mb);
            bulk_ld(buf+16384,  (const char*)Alg + (size_t)(m0*16+kt+2)*16384, 16384, mb);
            bulk_ld(buf+32768,  (const char*)Bhg + (size_t)(n0*16+kt+2)*16384, 16384, mb);
            bulk_ld(buf+49152,  (const char*)Blg + (size_t)(n0*16+kt+2)*16384, 16384, mb);
        }
    }

    const int bm = m0*128, bn = n0*128;
    const int g = lane>>2, tg = lane&3;
    bf16* outh = (z==0) ? g_qh : (z==1) ? g_kh : g_vh;
    bf16* outl = (z==0) ? g_ql : (z==1) ? g_kl : g_vl;
    const int mode = qkv ? ((z==2) ? 0 : 1) : 2;
#pragma unroll
    for (int mi=0; mi<4; mi++)
#pragma unroll
    for (int ni=0; ni<4; ni++){
        const int r0 = bm+wm+mi*16+g;
        const int c  = bn+wn+ni*8+tg*2;
        const float2 bv = *reinterpret_cast<const float2*>(&bias[c]);
        const float x0=acc[mi][ni][0]+bv.x, x1=acc[mi][ni][1]+bv.y;
        const float x2=acc[mi][ni][2]+bv.x, x3=acc[mi][ni][3]+bv.y;
        if (mode == 2){
            const float2 q0 = *reinterpret_cast<const float2*>(&resid[(size_t)r0*Dq + c]);
            const float2 q1 = *reinterpret_cast<const float2*>(&resid[(size_t)(r0+8)*Dq + c]);
            *reinterpret_cast<float2*>(&outf[(size_t)r0*Dq+c])     = make_float2(x0+q0.x, x1+q0.y);
            *reinterpret_cast<float2*>(&outf[(size_t)(r0+8)*Dq+c]) = make_float2(x2+q1.x, x3+q1.y);
        } else if (mode == 1){
            bf16 h0,l0,h1,l1;
#pragma unroll
            for (int hh = 0; hh < 2; hh++){
                const int rr = r0 + hh*8;
                const size_t tb = ((size_t)(rr>>7)*16 + (c>>6)) * 16384;
                const uint32_t off = SWZ(((rr&127)<<7) + ((c&63)<<1));
                const float y0 = hh ? x2 : x0;
                const float y1 = hh ? x3 : x1;
                split2(y0,h0,l0); split2(y1,h1,l1);
                *reinterpret_cast<bf162*>((char*)outh + tb + off) = __halves2bfloat162(h0,h1);
                *reinterpret_cast<bf162*>((char*)outl + tb + off) = __halves2bfloat162(l0,l1);
            }
        } else {
            bf16 h0,l0,h1,l1;
            split2(x0,h0,l0); split2(x1,h1,l1);
            *reinterpret_cast<bf162*>(&outh[(size_t)r0*Dq+c]) = __halves2bfloat162(h0,h1);
            *reinterpret_cast<bf162*>(&outl[(size_t)r0*Dq+c]) = __halves2bfloat162(l0,l1);
            split2(x2,h0,l0); split2(x3,h1,l1);
            *reinterpret_cast<bf162*>(&outh[(size_t)(r0+8)*Dq+c]) = __halves2bfloat162(h0,h1);
            *reinterpret_cast<bf162*>(&outl[(size_t)(r0+8)*Dq+c]) = __halves2bfloat162(l0,l1);
        }
    }
}

// ============================================================
// Scores (bulk-TMA) — unchanged
// ============================================================
#define SC_SMEM (128 + 65536)

__global__ __launch_bounds__(256) void scores_kernel(float* __restrict__ scores)
{
    extern __shared__ __align__(128) char sm_[];
    const int bh = blockIdx.z, b = bh>>4, h = bh&15;
    const int tid = threadIdx.x, lane = tid&31, warp = tid>>5;
    const int bm = blockIdx.y*128, bn = blockIdx.x*128;
    const uint32_t sb = s2u(sm_);
    const uint32_t dat = sb + 128;

    const size_t atile = ((size_t)(b*16 + blockIdx.y)*16 + h) * 16384;
    const size_t btile = ((size_t)(b*16 + blockIdx.x)*16 + h) * 16384;

    if (tid == 0){
        mbar_init(sb, 1);
    }
    __syncthreads();
    if (tid == 0){
        mbar_expect(sb, 65536);
        bulk_ld(dat,        (const char*)g_qh + atile, 16384, sb);
        bulk_ld(dat+16384,  (const char*)g_ql + atile, 16384, sb);
        bulk_ld(dat+32768,  (const char*)g_kh + btile, 16384, sb);
        bulk_ld(dat+49152,  (const char*)g_kl + btile, 16384, sb);
    }

    const int wm = (warp>>2)*64, wn = (warp&3)*32;
    float acc[4][4][4] = {};

    mbar_wait(sb, 0);

#pragma unroll
    for (int ks = 0; ks < 4; ks++){
        uint32_t bhf[4][2], blf[4][2];
#pragma unroll
        for (int p = 0; p < 2; p++){
            const uint32_t roff = (uint32_t)(wn + p*16 + (lane&7) + ((lane>>4)&1)*8)*128
                                  + ks*32 + ((lane>>3)&1)*16;
            ldm4(dat + 32768 + SWZ(roff), bhf[2*p][0], bhf[2*p][1], bhf[2*p+1][0], bhf[2*p+1][1]);
            ldm4(dat + 49152 + SWZ(roff), blf[2*p][0], blf[2*p][1], blf[2*p+1][0], blf[2*p+1][1]);
        }
#pragma unroll
        for (int mi = 0; mi < 4; mi++){
            const uint32_t roff = (uint32_t)(wm + mi*16 + (lane&15))*128
                                  + ks*32 + ((lane>>4)&1)*16;
            uint32_t a0,a1,a2,a3, l0,l1,l2,l3;
            ldm4(dat +         SWZ(roff), a0,a1,a2,a3);
            ldm4(dat + 16384 + SWZ(roff), l0,l1,l2,l3);
#pragma unroll
            for (int ni = 0; ni < 4; ni++){
                mma16(acc[mi][ni], a0,a1,a2,a3, bhf[ni][0], bhf[ni][1]);
                mma16(acc[mi][ni], a0,a1,a2,a3, blf[ni][0], blf[ni][1]);
                mma16(acc[mi][ni], l0,l1,l2,l3, bhf[ni][0], bhf[ni][1]);
            }
        }
    }

    __shared__ float psum[128][4];
    float* C = scores + (size_t)bh*Sq*Sq;
    const int g=lane>>2, tg=lane&3;
    const int wnidx = warp & 3;
#pragma unroll
    for (int mi=0; mi<4; mi++){
        float s0 = 0.f, s1 = 0.f;
#pragma unroll
        for (int ni=0; ni<4; ni++){
            const int r0 = bm+wm+mi*16+g;
            const int c  = bn+wn+ni*8+tg*2;
            const float e0 = __expf(acc[mi][ni][0]*0.125f);
            const float e1 = __expf(acc[mi][ni][1]*0.125f);
            const float e2 = __expf(acc[mi][ni][2]*0.125f);
            const float e3 = __expf(acc[mi][ni][3]*0.125f);
            *reinterpret_cast<float2*>(&C[(size_t)r0*Sq+c])     = make_float2(e0, e1);
            *reinterpret_cast<float2*>(&C[(size_t)(r0+8)*Sq+c]) = make_float2(e2, e3);
            s0 += e0 + e1;
            s1 += e2 + e3;
        }
        s0 += __shfl_xor_sync(0xffffffffu, s0, 1);
        s0 += __shfl_xor_sync(0xffffffffu, s0, 2);
        s1 += __shfl_xor_sync(0xffffffffu, s1, 1);
        s1 += __shfl_xor_sync(0xffffffffu, s1, 2);
        if (tg == 0){
            psum[wm+mi*16+g][wnidx]   = s0;
            psum[wm+mi*16+g+8][wnidx] = s1;
        }
    }
    __syncthreads();
    if (tid < 128){
        const float t = psum[tid][0] + psum[tid][1] + psum[tid][2] + psum[tid][3];
        g_psum[((size_t)bh*16 + blockIdx.x)*Sq + bm + tid] = t;
    }
}

// ============================================================
// av (rebuilt): BK=32, 3-stage cp.async ring for P f32 + V split,
// normalized-P STG + split-to-smem + mma. 2 CTAs/SM.
// stage: P f32 128x32 pitch144 (18432) | Vh 32x64 pitch144 (4608) | Vl (4608)
// E smem: hi/lo 128 rows x 32 k, pitch 80 (10240 each)
// ============================================================
#define AV_PP    144
#define AV_PSTG  (128*AV_PP)             // 18432
#define AV_VSTG  (32*144)                // 4608
#define AV_STG3  (AV_PSTG + 2*AV_VSTG)   // 27648
#define AV_EP    80
#define AV_EH    (128*AV_EP)             // 10240
#define AV_SMEM  (512 + 3*AV_STG3 + 2*AV_EH)   // 103936

__global__ __launch_bounds__(256,2) void av_kernel(float* __restrict__ scores)
{
    extern __shared__ __align__(128) char sm_[];
    const int qt = blockIdx.x, bh = blockIdx.y, b = bh>>4, h = bh&15;
    const int bm = qt*128;
    const int tid = threadIdx.x, lane = tid&31, warp = tid>>5;
    float* P = scores + (size_t)bh*Sq*Sq;
    const bf16* Vhg = g_vh + (size_t)b*Sq*Dq + h*DHq;
    const bf16* Vlg = g_vl + (size_t)b*Sq*Dq + h*DHq;

    float* invs = reinterpret_cast<float*>(sm_);
    const uint32_t su = s2u(sm_ + 512);          // stages base
    const uint32_t eu = su + 3*AV_STG3;          // Eh base (El at +AV_EH)

    // inv row sums
    if (tid < 128){
        float s = 0.f;
#pragma unroll
        for (int t = 0; t < 16; t++)
            s += g_psum[((size_t)bh*16 + t)*Sq + bm + tid];
        invs[tid] = 1.0f / s;
    }

    // stage fill: k-tile kt (32 k cols) into stage p
    auto fill = [&](int p, int kt){
        const int k0 = kt*32;
        const uint32_t sbase = su + (uint32_t)p*AV_STG3;
#pragma unroll
        for (int c = 0; c < 4; c++){
            const int ch = tid + c*256;           // 0..1023
            const int rr = ch >> 3, cc = ch & 7;  // row, 16B chunk
            cpa16(sbase + (uint32_t)(rr*AV_PP + cc*16),
                  &P[(size_t)(bm + rr)*Sq + k0 + cc*4]);
        }
#pragma unroll
        for (int c = 0; c < 2; c++){
            const int ch = tid + c*256;           // 0..511
            const int part = ch >> 8, idx = ch & 255;
            const int vr = idx >> 3, vc = idx & 7;
            const bf16* src = part ? Vlg : Vhg;
            cpa16(sbase + AV_PSTG + (uint32_t)(part*AV_VSTG + vr*144 + vc*16),
                  src + (size_t)(k0 + vr)*Dq + vc*8);
        }
        cpcommit();
    };

    fill(0, 0); fill(1, 1); fill(2, 2);
    __syncthreads();   // invs visible

    const int pr = tid>>1, pc0 = (tid&1)*16;     // split mapping: row, col base
    const float inv = invs[pr];
    const int wm = (warp>>1)*32, wn = (warp&1)*32;

    float acc[2][4][4] = {};

    for (int kt = 0; kt < 64; kt++){
        const int s = kt % 3;
        asm volatile("cp.async.wait_group 1;\n" ::: "memory");
        __syncthreads();                          // B1: stage s ready; prev mma done

        if (kt >= 1 && kt+2 < 64)
            fill((kt+2)%3, kt+2);                 // refill stage consumed at kt-1

        // split stage-s P: normalize, STG to d_out, split to E smem
        {
            const char* ps = sm_ + 512 + s*AV_STG3;
            char* EhB = sm_ + 512 + 3*AV_STG3;
#pragma unroll
            for (int j = 0; j < 4; j++){
                const int c = pc0 + j*4;
                float4 v = *reinterpret_cast<const float4*>(ps + pr*AV_PP + c*4);
                v.x *= inv; v.y *= inv; v.z *= inv; v.w *= inv;
                *reinterpret_cast<float4*>(&P[(size_t)(bm + pr)*Sq + kt*32 + c]) = v;
                bf16 h0,l0,h1,l1,h2,l2,h3,l3;
                split2(v.x,h0,l0); split2(v.y,h1,l1); split2(v.z,h2,l2); split2(v.w,h3,l3);
                char* eh = EhB + pr*AV_EP + c*2;
                *reinterpret_cast<bf162*>(eh)            = __halves2bfloat162(h0,h1);
                *reinterpret_cast<bf162*>(eh+4)          = __halves2bfloat162(h2,h3);
                *reinterpret_cast<bf162*>(eh + AV_EH)    = __halves2bfloat162(l0,l1);
                *reinterpret_cast<bf162*>(eh + AV_EH+4)  = __halves2bfloat162(l2,l3);
            }
        }
        __syncthreads();                          // B2: E visible

        const uint32_t stv = su + (uint32_t)s*AV_STG3 + AV_PSTG;
#pragma unroll
        for (int ks = 0; ks < 2; ks++){
            uint32_t bhf[4][2], blf[4][2];
#pragma unroll
            for (int p = 0; p < 2; p++){
                const uint32_t ro = (uint32_t)(ks*16*144 + ((lane>>3)&1)*8*144 + (lane&7)*144
                                    + (wn + p*16 + ((lane>>4)&1)*8)*2);
                ldm4t(stv + ro,          bhf[2*p][0], bhf[2*p][1], bhf[2*p+1][0], bhf[2*p+1][1]);
                ldm4t(stv + AV_VSTG + ro, blf[2*p][0], blf[2*p][1], blf[2*p+1][0], blf[2*p+1][1]);
            }
#pragma unroll
            for (int mi = 0; mi < 2; mi++){
                const uint32_t ao = (uint32_t)((wm + mi*16 + (lane&15))*AV_EP
                                    + ks*32 + ((lane>>4)&1)*16);
                uint32_t a0,a1,a2,a3, l0,l1,l2,l3;
                ldm4(eu + ao,         a0,a1,a2,a3);
                ldm4(eu + AV_EH + ao, l0,l1,l2,l3);
#pragma unroll
                for (int ni = 0; ni < 4; ni++){
                    mma16(acc[mi][ni], a0,a1,a2,a3, bhf[ni][0], bhf[ni][1]);
                    mma16(acc[mi][ni], a0,a1,a2,a3, blf[ni][0], blf[ni][1]);
                    mma16(acc[mi][ni], l0,l1,l2,l3, bhf[ni][0], bhf[ni][1]);
                }
            }
        }
    }

    // epilogue: ctx (already normalized) -> tile-major (tile col = head)
    const int g = lane>>2, tg = lane&3;
#pragma unroll
    for (int mi = 0; mi < 2; mi++)
#pragma unroll
    for (int ni = 0; ni < 4; ni++){
        const int r0 = bm + wm + mi*16 + g;
        const int c  = wn + ni*8 + tg*2;
#pragma unroll
        for (int hh = 0; hh < 2; hh++){
            const int grow = b*Sq + r0 + hh*8;
            const size_t tb = ((size_t)((grow>>7)*16 + h)) * 16384;
            const uint32_t off = SWZ(((grow&127)<<7) + (c<<1));
            const float x0 = acc[mi][ni][hh*2+0];
            const float x1 = acc[mi][ni][hh*2+1];
            bf16 h0,l0,h1,l1;
            split2(x0,h0,l0); split2(x1,h1,l1);
            *reinterpret_cast<bf162*>((char*)g_pch + tb + off) = __halves2bfloat162(h0,h1);
            *reinterpret_cast<bf162*>((char*)g_pcl + tb + off) = __halves2bfloat162(l0,l1);
        }
    }
}

// ============================================================
// LayerNorm per row of g_y -> d_out
// ============================================================
__global__ void ln_kernel(const float* __restrict__ gamma,
                          const float* __restrict__ beta,
                          float* __restrict__ out)
{
    const size_t row = blockIdx.x;
    const float4* y = reinterpret_cast<const float4*>(g_y + row * (size_t)Dq);
    float4* o = reinterpret_cast<float4*>(out + row * (size_t)Dq);
    const int tid = threadIdx.x;
    __shared__ float sm[8], sm2[8];

    float4 v = y[tid];
    float s  = v.x + v.y + v.z + v.w;
    float s2 = v.x*v.x + v.y*v.y + v.z*v.z + v.w*v.w;
#pragma unroll
    for (int o2 = 16; o2 > 0; o2 >>= 1) {
        s  += __shfl_xor_sync(0xffffffffu, s,  o2);
        s2 += __shfl_xor_sync(0xffffffffu, s2, o2);
    }
    if ((tid & 31) == 0) { sm[tid>>5] = s; sm2[tid>>5] = s2; }
    __syncthreads();
    float ts = 0.f, ts2 = 0.f;
#pragma unroll
    for (int w = 0; w < 8; w++) { ts += sm[w]; ts2 += sm2[w]; }
    const float mean = ts * (1.0f/Dq);
    const float var  = ts2 * (1.0f/Dq) - mean*mean;
    const float rstd = rsqrtf(var + 1e-6f);

    const float4 gg = reinterpret_cast<const float4*>(gamma)[tid];
    const float4 bb = reinterpret_cast<const float4*>(beta)[tid];
    float4 r;
    r.x = (v.x - mean) * rstd * gg.x + bb.x;
    r.y = (v.y - mean) * rstd * gg.y + bb.y;
    r.z = (v.z - mean) * rstd * gg.z + bb.z;
    r.w = (v.w - mean) * rstd * gg.w + bb.w;
    o[tid] = r;
}

// ============================================================
extern "C" void kernel_launch(void* const* d_in, const int* in_sizes, int n_in,
                              void* d_out, int out_size)
{
    const float* Q     = (const float*)d_in[0];
    const float* K     = (const float*)d_in[1];
    const float* V     = (const float*)d_in[2];
    const float* Wq    = (const float*)d_in[3];
    const float* bq    = (const float*)d_in[4];
    const float* Wk    = (const float*)d_in[5];
    const float* bk    = (const float*)d_in[6];
    const float* Wv    = (const float*)d_in[7];
    const float* bv    = (const float*)d_in[8];
    const float* Wo    = (const float*)d_in[9];
    const float* bo    = (const float*)d_in[10];
    const float* gamma = (const float*)d_in[11];
    const float* beta  = (const float*)d_in[12];

    float* out    = (float*)d_out;
    float* scores = out + OUT_OFF;

    bf16 *pah, *pal, *pwh, *pwl, *pch, *pcl;
    float* gy;
    cudaGetSymbolAddress((void**)&pah,  g_pah);
    cudaGetSymbolAddress((void**)&pal,  g_pal);
    cudaGetSymbolAddress((void**)&pwh,  g_pwh);
    cudaGetSymbolAddress((void**)&pwl,  g_pwl);
    cudaGetSymbolAddress((void**)&pch,  g_pch);
    cudaGetSymbolAddress((void**)&pcl,  g_pcl);
    cudaGetSymbolAddress((void**)&gy,   g_y);

    static bool attr_set = false;
    if (!attr_set){
        cudaFuncSetAttribute(proj_kernel,   cudaFuncAttributeMaxDynamicSharedMemorySize, PR_SMEM);
        cudaFuncSetAttribute(scores_kernel, cudaFuncAttributeMaxDynamicSharedMemorySize, SC_SMEM);
        cudaFuncSetAttribute(av_kernel,     cudaFuncAttributeMaxDynamicSharedMemorySize, AV_SMEM);
        attr_set = true;
    }

    dim3 blk(256);

    // all 7 splits in one launch
    dim3 gSp(4096, 7);
    split_all<<<gSp, blk>>>(Q, K, V, Wq, Wk, Wv, Wo);

    // merged QKV projections
    dim3 gP3(8, 32, 3);
    proj_kernel<<<gP3, blk, PR_SMEM>>>(pah, pal, pwh, pwl,
                                       bq, bk, bv, nullptr, nullptr, 1);

    // scores -> E f32 + partial row sums
    dim3 gSc(Sq/128, Sq/128, Bq*Hq);
    scores_kernel<<<gSc, blk, SC_SMEM>>>(scores);

    // av: staged P/V, normalized-P writeback + PV mma
    dim3 gAv(16, 32);
    av_kernel<<<gAv, blk, AV_SMEM>>>(scores);

    // O projection + bias + residual -> g_y
    dim3 gP1(8, 32, 1);
    proj_kernel<<<gP1, blk, PR_SMEM>>>(pch, pcl, pwh + 3*(size_t)WN, pwl + 3*(size_t)WN,
                                       bo, bo, bo, Q, gy, 0);

    ln_kernel<<<(unsigned)Mq, blk>>>(gamma, beta, out);
}

// round 13
// speedup vs baseline: 1.0559x; 1.0559x over previous
#include <cuda_runtime.h>
#include <cuda_bf16.h>
#include <math.h>
#include <stdint.h>

#define Bq 2
#define Sq 2048
#define Dq 1024
#define Hq 16
#define DHq 64
#define Mq (Bq*Sq)
#define NELEM (Mq*Dq)
#define WN (Dq*Dq)
#define OUT_OFF ((size_t)Mq*Dq)

typedef __nv_bfloat16 bf16;
typedef __nv_bfloat162 bf162;

// SW128 swizzle (byte offsets)
#define SWZ(x) ((x) ^ ((((uint32_t)(x))>>3)&0x70))

// ---------------- global scratch (no allocs allowed) ----------------
__device__ __align__(16) bf16 g_pah[3][NELEM], g_pal[3][NELEM];   // inputs Q,K,V
__device__ __align__(16) bf16 g_pwh[4][WN],    g_pwl[4][WN];      // weights
__device__ __align__(16) bf16 g_pch[NELEM],    g_pcl[NELEM];      // ctx (tile-major)
__device__ __align__(16) bf16 g_qh[NELEM], g_ql[NELEM];           // q tile-major
__device__ __align__(16) bf16 g_kh[NELEM], g_kl[NELEM];           // k tile-major
__device__ __align__(16) bf16 g_vh[NELEM], g_vl[NELEM];           // v row-major
__device__ float g_y[NELEM];
__device__ float g_psum[(size_t)Bq*Hq*16*Sq];
// E = exp(S/8) scratch (separate region from d_out to avoid same-address RMW)
__device__ __align__(16) float g_e[(size_t)Bq*Hq*Sq*Sq];

// ---------------- helpers ----------------
__device__ __forceinline__ uint32_t s2u(const void* p){ return (uint32_t)__cvta_generic_to_shared(p); }
__device__ __forceinline__ void cpa16(uint32_t s, const void* g){
    asm volatile("cp.async.cg.shared.global [%0], [%1], 16;\n" :: "r"(s), "l"(g));
}
__device__ __forceinline__ void cpcommit(){ asm volatile("cp.async.commit_group;\n" ::: "memory"); }
__device__ __forceinline__ void ldm4(uint32_t a, uint32_t&r0,uint32_t&r1,uint32_t&r2,uint32_t&r3){
    asm volatile("ldmatrix.sync.aligned.m8n8.x4.shared.b16 {%0,%1,%2,%3}, [%4];\n"
        : "=r"(r0),"=r"(r1),"=r"(r2),"=r"(r3) : "r"(a));
}
__device__ __forceinline__ void ldm4t(uint32_t a, uint32_t&r0,uint32_t&r1,uint32_t&r2,uint32_t&r3){
    asm volatile("ldmatrix.sync.aligned.m8n8.x4.trans.shared.b16 {%0,%1,%2,%3}, [%4];\n"
        : "=r"(r0),"=r"(r1),"=r"(r2),"=r"(r3) : "r"(a));
}
__device__ __forceinline__ void mma16(float* c, uint32_t a0,uint32_t a1,uint32_t a2,uint32_t a3,
                                      uint32_t b0,uint32_t b1){
    asm volatile("mma.sync.aligned.m16n8k16.row.col.f32.bf16.bf16.f32 "
        "{%0,%1,%2,%3}, {%4,%5,%6,%7}, {%8,%9}, {%0,%1,%2,%3};\n"
        : "+f"(c[0]),"+f"(c[1]),"+f"(c[2]),"+f"(c[3])
        : "r"(a0),"r"(a1),"r"(a2),"r"(a3),"r"(b0),"r"(b1));
}
__device__ __forceinline__ void split2(float x, bf16& h, bf16& l){
    h = __float2bfloat16(x);
    l = __float2bfloat16(x - __bfloat162float(h));
}

// ---- bulk TMA + mbarrier ----
__device__ __forceinline__ void bulk_ld(uint32_t dst, const void* src, uint32_t bytes, uint32_t mbar){
    asm volatile("cp.async.bulk.shared::cta.global.mbarrier::complete_tx::bytes [%0], [%1], %2, [%3];\n"
        :: "r"(dst), "l"(src), "r"(bytes), "r"(mbar) : "memory");
}
__device__ __forceinline__ void mbar_init(uint32_t mbar, uint32_t cnt){
    asm volatile("mbarrier.init.shared.b64 [%0], %1;\n" :: "r"(mbar), "r"(cnt) : "memory");
}
__device__ __forceinline__ void mbar_expect(uint32_t mbar, uint32_t tx){
    asm volatile("mbarrier.arrive.expect_tx.shared.b64 _, [%0], %1;\n" :: "r"(mbar), "r"(tx) : "memory");
}
__device__ __forceinline__ void mbar_wait(uint32_t mbar, uint32_t parity){
    asm volatile("{\n\t.reg .pred P;\n\t"
        "W%=:\n\t"
        "mbarrier.try_wait.parity.acquire.cta.shared::cta.b64 P, [%0], %1, 0x989680;\n\t"
        "@!P bra W%=;\n\t}\n"
        :: "r"(mbar), "r"(parity) : "memory");
}

// ---------------- split all 7 f32 matrices in ONE launch ----------------
__global__ void split_all(const float* __restrict__ Q, const float* __restrict__ K,
                          const float* __restrict__ V, const float* __restrict__ W0,
                          const float* __restrict__ W1, const float* __restrict__ W2,
                          const float* __restrict__ W3)
{
    const int y = blockIdx.y;
    const float* src;
    bf16 *th, *tl;
    int n4;
    if (y < 3){
        src = (y==0) ? Q : (y==1) ? K : V;
        th = g_pah[y]; tl = g_pal[y]; n4 = NELEM/4;
    } else {
        const int w = y - 3;
        src = (w==0) ? W0 : (w==1) ? W1 : (w==2) ? W2 : W3;
        th = g_pwh[w]; tl = g_pwl[w]; n4 = WN/4;
    }
    const int i = blockIdx.x*blockDim.x + threadIdx.x;
    if (i >= n4) return;
    const int r = i >> 8, c4 = (i & 255) << 2;
    float4 v = reinterpret_cast<const float4*>(src)[i];
    bf16 h0,l0,h1,l1,h2,l2,h3,l3;
    split2(v.x,h0,l0); split2(v.y,h1,l1); split2(v.z,h2,l2); split2(v.w,h3,l3);
    const size_t tile = (size_t)((r>>7)*16 + (c4>>6)) * 16384;
    const uint32_t off = SWZ(((r&127)<<7) + ((c4&63)<<1));
    char* dh = (char*)th + tile + off;
    char* dl = (char*)tl + tile + off;
    *reinterpret_cast<bf162*>(dh)   = __halves2bfloat162(h0,h1);
    *reinterpret_cast<bf162*>(dh+4) = __halves2bfloat162(h2,h3);
    *reinterpret_cast<bf162*>(dl)   = __halves2bfloat162(l0,l1);
    *reinterpret_cast<bf162*>(dl+4) = __halves2bfloat162(l2,l3);
}

// ============================================================
// Projection GEMM (NT, mma.sync, bulk-TMA staged) — unchanged
// ============================================================
#define PR_STAGE 65536
#define PR_SMEM  (128 + 2*PR_STAGE)

__global__ __launch_bounds__(256,1) void proj_kernel(
    const bf16* __restrict__ Ahg0, const bf16* __restrict__ Alg0,
    const bf16* __restrict__ Bhg0, const bf16* __restrict__ Blg0,
    const float* __restrict__ bias0, const float* __restrict__ bias1,
    const float* __restrict__ bias2, const float* __restrict__ resid,
    float* __restrict__ outf, int qkv)
{
    extern __shared__ __align__(128) char sm_[];
    const int tid = threadIdx.x, lane = tid&31, warp = tid>>5;
    const int n0 = blockIdx.x, m0 = blockIdx.y, z = blockIdx.z;
    const bf16* Ahg = Ahg0 + (size_t)z*NELEM;
    const bf16* Alg = Alg0 + (size_t)z*NELEM;
    const bf16* Bhg = Bhg0 + (size_t)z*WN;
    const bf16* Blg = Blg0 + (size_t)z*WN;
    const float* bias = (z==0) ? bias0 : (z==1) ? bias1 : bias2;
    const uint32_t sb = s2u(sm_);
    const uint32_t dat = sb + 128;

    if (tid == 0){
        mbar_init(sb+0, 1);
        mbar_init(sb+8, 1);
#pragma unroll
        for (int p = 0; p < 2; p++){
            const uint32_t mb = sb + p*8;
            const uint32_t buf = dat + p*PR_STAGE;
            mbar_expect(mb, PR_STAGE);
            bulk_ld(buf,        (const char*)Ahg + (size_t)(m0*16+p)*16384, 16384, mb);
            bulk_ld(buf+16384,  (const char*)Alg + (size_t)(m0*16+p)*16384, 16384, mb);
            bulk_ld(buf+32768,  (const char*)Bhg + (size_t)(n0*16+p)*16384, 16384, mb);
            bulk_ld(buf+49152,  (const char*)Blg + (size_t)(n0*16+p)*16384, 16384, mb);
        }
    }
    __syncthreads();

    const int wm = (warp>>2)*64, wn = (warp&3)*32;
    float acc[4][4][4] = {};

    for (int kt = 0; kt < 16; kt++){
        const int b = kt & 1;
        mbar_wait(sb + b*8, (kt>>1)&1);
        const uint32_t buf = dat + b*PR_STAGE;
#pragma unroll
        for (int ks = 0; ks < 4; ks++){
            uint32_t bhf[4][2], blf[4][2];
#pragma unroll
            for (int p = 0; p < 2; p++){
                const uint32_t roff = (uint32_t)(wn + p*16 + (lane&7) + ((lane>>4)&1)*8)*128
                                      + ks*32 + ((lane>>3)&1)*16;
                ldm4(buf + 32768 + SWZ(roff), bhf[2*p][0], bhf[2*p][1], bhf[2*p+1][0], bhf[2*p+1][1]);
                ldm4(buf + 49152 + SWZ(roff), blf[2*p][0], blf[2*p][1], blf[2*p+1][0], blf[2*p+1][1]);
            }
#pragma unroll
            for (int mi = 0; mi < 4; mi++){
                const uint32_t roff = (uint32_t)(wm + mi*16 + (lane&15))*128
                                      + ks*32 + ((lane>>4)&1)*16;
                uint32_t a0,a1,a2,a3, l0,l1,l2,l3;
                ldm4(buf +         SWZ(roff), a0,a1,a2,a3);
                ldm4(buf + 16384 + SWZ(roff), l0,l1,l2,l3);
#pragma unroll
                for (int ni = 0; ni < 4; ni++){
                    mma16(acc[mi][ni], a0,a1,a2,a3, bhf[ni][0], bhf[ni][1]);
                    mma16(acc[mi][ni], a0,a1,a2,a3, blf[ni][0], blf[ni][1]);
                    mma16(acc[mi][ni], l0,l1,l2,l3, bhf[ni][0], bhf[ni][1]);
                }
            }
        }
        __syncthreads();
        if (tid == 0 && kt+2 < 16){
            const uint32_t mb = sb + b*8;
            mbar_expect(mb, PR_STAGE);
            bulk_ld(buf,        (const char*)Ahg + (size_t)(m0*16+kt+2)*16384, 16384, mb);
            bulk_ld(buf+16384,  (const char*)Alg + (size_t)(m0*16+kt+2)*16384, 16384, mb);
            bulk_ld(buf+32768,  (const char*)Bhg + (size_t)(n0*16+kt+2)*16384, 16384, mb);
            bulk_ld(buf+49152,  (const char*)Blg + (size_t)(n0*16+kt+2)*16384, 16384, mb);
        }
    }

    const int bm = m0*128, bn = n0*128;
    const int g = lane>>2, tg = lane&3;
    bf16* outh = (z==0) ? g_qh : (z==1) ? g_kh : g_vh;
    bf16* outl = (z==0) ? g_ql : (z==1) ? g_kl : g_vl;
    const int mode = qkv ? ((z==2) ? 0 : 1) : 2;
#pragma unroll
    for (int mi=0; mi<4; mi++)
#pragma unroll
    for (int ni=0; ni<4; ni++){
        const int r0 = bm+wm+mi*16+g;
        const int c  = bn+wn+ni*8+tg*2;
        const float2 bv = *reinterpret_cast<const float2*>(&bias[c]);
        const float x0=acc[mi][ni][0]+bv.x, x1=acc[mi][ni][1]+bv.y;
        const float x2=acc[mi][ni][2]+bv.x, x3=acc[mi][ni][3]+bv.y;
        if (mode == 2){
            const float2 q0 = *reinterpret_cast<const float2*>(&resid[(size_t)r0*Dq + c]);
            const float2 q1 = *reinterpret_cast<const float2*>(&resid[(size_t)(r0+8)*Dq + c]);
            *reinterpret_cast<float2*>(&outf[(size_t)r0*Dq+c])     = make_float2(x0+q0.x, x1+q0.y);
            *reinterpret_cast<float2*>(&outf[(size_t)(r0+8)*Dq+c]) = make_float2(x2+q1.x, x3+q1.y);
        } else if (mode == 1){
            bf16 h0,l0,h1,l1;
#pragma unroll
            for (int hh = 0; hh < 2; hh++){
                const int rr = r0 + hh*8;
                const size_t tb = ((size_t)(rr>>7)*16 + (c>>6)) * 16384;
                const uint32_t off = SWZ(((rr&127)<<7) + ((c&63)<<1));
                const float y0 = hh ? x2 : x0;
                const float y1 = hh ? x3 : x1;
                split2(y0,h0,l0); split2(y1,h1,l1);
                *reinterpret_cast<bf162*>((char*)outh + tb + off) = __halves2bfloat162(h0,h1);
                *reinterpret_cast<bf162*>((char*)outl + tb + off) = __halves2bfloat162(l0,l1);
            }
        } else {
            bf16 h0,l0,h1,l1;
            split2(x0,h0,l0); split2(x1,h1,l1);
            *reinterpret_cast<bf162*>(&outh[(size_t)r0*Dq+c]) = __halves2bfloat162(h0,h1);
            *reinterpret_cast<bf162*>(&outl[(size_t)r0*Dq+c]) = __halves2bfloat162(l0,l1);
            split2(x2,h0,l0); split2(x3,h1,l1);
            *reinterpret_cast<bf162*>(&outh[(size_t)(r0+8)*Dq+c]) = __halves2bfloat162(h0,h1);
            *reinterpret_cast<bf162*>(&outl[(size_t)(r0+8)*Dq+c]) = __halves2bfloat162(l0,l1);
        }
    }
}

// ============================================================
// Scores (bulk-TMA): E -> g_e scratch (NOT d_out) + partial row sums
// ============================================================
#define SC_SMEM (128 + 65536)

__global__ __launch_bounds__(256) void scores_kernel(float* __restrict__ escr)
{
    extern __shared__ __align__(128) char sm_[];
    const int bh = blockIdx.z, b = bh>>4, h = bh&15;
    const int tid = threadIdx.x, lane = tid&31, warp = tid>>5;
    const int bm = blockIdx.y*128, bn = blockIdx.x*128;
    const uint32_t sb = s2u(sm_);
    const uint32_t dat = sb + 128;

    const size_t atile = ((size_t)(b*16 + blockIdx.y)*16 + h) * 16384;
    const size_t btile = ((size_t)(b*16 + blockIdx.x)*16 + h) * 16384;

    if (tid == 0){
        mbar_init(sb, 1);
    }
    __syncthreads();
    if (tid == 0){
        mbar_expect(sb, 65536);
        bulk_ld(dat,        (const char*)g_qh + atile, 16384, sb);
        bulk_ld(dat+16384,  (const char*)g_ql + atile, 16384, sb);
        bulk_ld(dat+32768,  (const char*)g_kh + btile, 16384, sb);
        bulk_ld(dat+49152,  (const char*)g_kl + btile, 16384, sb);
    }

    const int wm = (warp>>2)*64, wn = (warp&3)*32;
    float acc[4][4][4] = {};

    mbar_wait(sb, 0);

#pragma unroll
    for (int ks = 0; ks < 4; ks++){
        uint32_t bhf[4][2], blf[4][2];
#pragma unroll
        for (int p = 0; p < 2; p++){
            const uint32_t roff = (uint32_t)(wn + p*16 + (lane&7) + ((lane>>4)&1)*8)*128
                                  + ks*32 + ((lane>>3)&1)*16;
            ldm4(dat + 32768 + SWZ(roff), bhf[2*p][0], bhf[2*p][1], bhf[2*p+1][0], bhf[2*p+1][1]);
            ldm4(dat + 49152 + SWZ(roff), blf[2*p][0], blf[2*p][1], blf[2*p+1][0], blf[2*p+1][1]);
        }
#pragma unroll
        for (int mi = 0; mi < 4; mi++){
            const uint32_t roff = (uint32_t)(wm + mi*16 + (lane&15))*128
                                  + ks*32 + ((lane>>4)&1)*16;
            uint32_t a0,a1,a2,a3, l0,l1,l2,l3;
            ldm4(dat +         SWZ(roff), a0,a1,a2,a3);
            ldm4(dat + 16384 + SWZ(roff), l0,l1,l2,l3);
#pragma unroll
            for (int ni = 0; ni < 4; ni++){
                mma16(acc[mi][ni], a0,a1,a2,a3, bhf[ni][0], bhf[ni][1]);
                mma16(acc[mi][ni], a0,a1,a2,a3, blf[ni][0], blf[ni][1]);
                mma16(acc[mi][ni], l0,l1,l2,l3, bhf[ni][0], bhf[ni][1]);
            }
        }
    }

    __shared__ float psum[128][4];
    float* C = escr + (size_t)bh*Sq*Sq;
    const int g=lane>>2, tg=lane&3;
    const int wnidx = warp & 3;
#pragma unroll
    for (int mi=0; mi<4; mi++){
        float s0 = 0.f, s1 = 0.f;
#pragma unroll
        for (int ni=0; ni<4; ni++){
            const int r0 = bm+wm+mi*16+g;
            const int c  = bn+wn+ni*8+tg*2;
            const float e0 = __expf(acc[mi][ni][0]*0.125f);
            const float e1 = __expf(acc[mi][ni][1]*0.125f);
            const float e2 = __expf(acc[mi][ni][2]*0.125f);
            const float e3 = __expf(acc[mi][ni][3]*0.125f);
            *reinterpret_cast<float2*>(&C[(size_t)r0*Sq+c])     = make_float2(e0, e1);
            *reinterpret_cast<float2*>(&C[(size_t)(r0+8)*Sq+c]) = make_float2(e2, e3);
            s0 += e0 + e1;
            s1 += e2 + e3;
        }
        s0 += __shfl_xor_sync(0xffffffffu, s0, 1);
        s0 += __shfl_xor_sync(0xffffffffu, s0, 2);
        s1 += __shfl_xor_sync(0xffffffffu, s1, 1);
        s1 += __shfl_xor_sync(0xffffffffu, s1, 2);
        if (tg == 0){
            psum[wm+mi*16+g][wnidx]   = s0;
            psum[wm+mi*16+g+8][wnidx] = s1;
        }
    }
    __syncthreads();
    if (tid < 128){
        const float t = psum[tid][0] + psum[tid][1] + psum[tid][2] + psum[tid][3];
        g_psum[((size_t)bh*16 + blockIdx.x)*Sq + bm + tid] = t;
    }
}

// ============================================================
// av v3: 64-row q tiles (grid 1024), 5-stage cp.async ring, wait_group 3.
// Reads E from g_e scratch, writes normalized P to d_out (separate regions).
// stage: E f32 64x32 pitch144 (9216) | Vh 32x64 p144 (4608) | Vl (4608) = 18432
// E-smem: hi/lo 64 x 32, pitch 80 (5120 each)
// ============================================================
#define AV_PP    144
#define AV_PSTG  (64*AV_PP)              // 9216
#define AV_VSTG  (32*144)                // 4608
#define AV_STG   (AV_PSTG + 2*AV_VSTG)   // 18432
#define AV_NST   5
#define AV_EP    80
#define AV_EH    (64*AV_EP)              // 5120
#define AV_SMEM  (512 + AV_NST*AV_STG + 2*AV_EH)   // 102912

__global__ __launch_bounds__(256,2) void av_kernel(const float* __restrict__ escr,
                                                   float* __restrict__ scores)
{
    extern __shared__ __align__(128) char sm_[];
    const int qt = blockIdx.x, bh = blockIdx.y, b = bh>>4, h = bh&15;
    const int bm = qt*64;
    const int tid = threadIdx.x, lane = tid&31, warp = tid>>5;
    const float* E = escr + (size_t)bh*Sq*Sq;
    float* P = scores + (size_t)bh*Sq*Sq;
    const bf16* Vhg = g_vh + (size_t)b*Sq*Dq + h*DHq;
    const bf16* Vlg = g_vl + (size_t)b*Sq*Dq + h*DHq;

    float* invs = reinterpret_cast<float*>(sm_);
    const uint32_t su = s2u(sm_ + 512);
    const uint32_t eu = su + AV_NST*AV_STG;

    if (tid < 64){
        float s = 0.f;
#pragma unroll
        for (int t = 0; t < 16; t++)
            s += g_psum[((size_t)bh*16 + t)*Sq + bm + tid];
        invs[tid] = 1.0f / s;
    }

    auto fill = [&](int p, int kt){
        const int k0 = kt*32;
        const uint32_t sbase = su + (uint32_t)p*AV_STG;
#pragma unroll
        for (int c = 0; c < 2; c++){
            const int ch = tid + c*256;              // 0..511
            const int rr = ch >> 3, cc = ch & 7;
            cpa16(sbase + (uint32_t)(rr*AV_PP + cc*16),
                  &E[(size_t)(bm + rr)*Sq + k0 + cc*4]);
        }
#pragma unroll
        for (int c = 0; c < 2; c++){
            const int ch = tid + c*256;              // 0..511
            const int part = ch >> 8, idx = ch & 255;
            const int vr = idx >> 3, vc = idx & 7;
            const bf16* src = part ? Vlg : Vhg;
            cpa16(sbase + AV_PSTG + (uint32_t)(part*AV_VSTG + vr*144 + vc*16),
                  src + (size_t)(k0 + vr)*Dq + vc*8);
        }
        cpcommit();
    };

    fill(0,0); fill(1,1); fill(2,2); fill(3,3);
    __syncthreads();   // invs visible

    const int pr = tid>>2, pc0 = (tid&3)*8;          // row 0..63, col base
    const float inv = invs[pr];
    const int wm = (warp>>1)*16, wn = (warp&1)*32;

    float acc[4][4] = {};

    for (int kt = 0; kt < 64; kt++){
        const int s = kt % AV_NST;
        asm volatile("cp.async.wait_group 3;\n" ::: "memory");
        __syncthreads();                              // stage s ready; prior reads done

        if (kt+4 < 64) fill((kt+4)%AV_NST, kt+4);

        // normalize + STG P + split to E-smem
        {
            const char* ps = sm_ + 512 + s*AV_STG;
            char* EhB = sm_ + 512 + AV_NST*AV_STG;
#pragma unroll
            for (int j = 0; j < 2; j++){
                const int c = pc0 + j*4;
                float4 v = *reinterpret_cast<const float4*>(ps + pr*AV_PP + c*4);
                v.x *= inv; v.y *= inv; v.z *= inv; v.w *= inv;
                *reinterpret_cast<float4*>(&P[(size_t)(bm + pr)*Sq + kt*32 + c]) = v;
                bf16 h0,l0,h1,l1,h2,l2,h3,l3;
                split2(v.x,h0,l0); split2(v.y,h1,l1); split2(v.z,h2,l2); split2(v.w,h3,l3);
                char* eh = EhB + pr*AV_EP + c*2;
                *reinterpret_cast<bf162*>(eh)           = __halves2bfloat162(h0,h1);
                *reinterpret_cast<bf162*>(eh+4)         = __halves2bfloat162(h2,h3);
                *reinterpret_cast<bf162*>(eh + AV_EH)   = __halves2bfloat162(l0,l1);
                *reinterpret_cast<bf162*>(eh + AV_EH+4) = __halves2bfloat162(l2,l3);
            }
        }
        __syncthreads();                              // E visible

        const uint32_t stv = su + (uint32_t)s*AV_STG + AV_PSTG;
#pragma unroll
        for (int ks = 0; ks < 2; ks++){
            uint32_t bhf[4][2], blf[4][2];
#pragma unroll
            for (int p = 0; p < 2; p++){
                const uint32_t ro = (uint32_t)((ks*16 + ((lane>>3)&1)*8 + (lane&7))*144
                                    + (wn + p*16 + ((lane>>4)&1)*8)*2);
                ldm4t(stv + ro,           bhf[2*p][0], bhf[2*p][1], bhf[2*p+1][0], bhf[2*p+1][1]);
                ldm4t(stv + AV_VSTG + ro, blf[2*p][0], blf[2*p][1], blf[2*p+1][0], blf[2*p+1][1]);
            }
            const uint32_t ao = (uint32_t)((wm + (lane&15))*AV_EP
                                + ks*32 + ((lane>>4)&1)*16);
            uint32_t a0,a1,a2,a3, l0,l1,l2,l3;
            ldm4(eu + ao,         a0,a1,a2,a3);
            ldm4(eu + AV_EH + ao, l0,l1,l2,l3);
#pragma unroll
            for (int ni = 0; ni < 4; ni++){
                mma16(acc[ni], a0,a1,a2,a3, bhf[ni][0], bhf[ni][1]);
                mma16(acc[ni], a0,a1,a2,a3, blf[ni][0], blf[ni][1]);
                mma16(acc[ni], l0,l1,l2,l3, bhf[ni][0], bhf[ni][1]);
            }
        }
    }

    // epilogue: ctx (normalized) -> tile-major (tile col = head)
    const int g = lane>>2, tg = lane&3;
#pragma unroll
    for (int ni = 0; ni < 4; ni++){
        const int r0 = bm + wm + g;
        const int c  = wn + ni*8 + tg*2;
#pragma unroll
        for (int hh = 0; hh < 2; hh++){
            const int grow = b*Sq + r0 + hh*8;
            const size_t tb = ((size_t)((grow>>7)*16 + h)) * 16384;
            const uint32_t off = SWZ(((grow&127)<<7) + (c<<1));
            const float x0 = acc[ni][hh*2+0];
            const float x1 = acc[ni][hh*2+1];
            bf16 h0,l0,h1,l1;
            split2(x0,h0,l0); split2(x1,h1,l1);
            *reinterpret_cast<bf162*>((char*)g_pch + tb + off) = __halves2bfloat162(h0,h1);
            *reinterpret_cast<bf162*>((char*)g_pcl + tb + off) = __halves2bfloat162(l0,l1);
        }
    }
}

// ============================================================
// LayerNorm per row of g_y -> d_out
// ============================================================
__global__ void ln_kernel(const float* __restrict__ gamma,
                          const float* __restrict__ beta,
                          float* __restrict__ out)
{
    const size_t row = blockIdx.x;
    const float4* y = reinterpret_cast<const float4*>(g_y + row * (size_t)Dq);
    float4* o = reinterpret_cast<float4*>(out + row * (size_t)Dq);
    const int tid = threadIdx.x;
    __shared__ float sm[8], sm2[8];

    float4 v = y[tid];
    float s  = v.x + v.y + v.z + v.w;
    float s2 = v.x*v.x + v.y*v.y + v.z*v.z + v.w*v.w;
#pragma unroll
    for (int o2 = 16; o2 > 0; o2 >>= 1) {
        s  += __shfl_xor_sync(0xffffffffu, s,  o2);
        s2 += __shfl_xor_sync(0xffffffffu, s2, o2);
    }
    if ((tid & 31) == 0) { sm[tid>>5] = s; sm2[tid>>5] = s2; }
    __syncthreads();
    float ts = 0.f, ts2 = 0.f;
#pragma unroll
    for (int w = 0; w < 8; w++) { ts += sm[w]; ts2 += sm2[w]; }
    const float mean = ts * (1.0f/Dq);
    const float var  = ts2 * (1.0f/Dq) - mean*mean;
    const float rstd = rsqrtf(var + 1e-6f);

    const float4 gg = reinterpret_cast<const float4*>(gamma)[tid];
    const float4 bb = reinterpret_cast<const float4*>(beta)[tid];
    float4 r;
    r.x = (v.x - mean) * rstd * gg.x + bb.x;
    r.y = (v.y - mean) * rstd * gg.y + bb.y;
    r.z = (v.z - mean) * rstd * gg.z + bb.z;
    r.w = (v.w - mean) * rstd * gg.w + bb.w;
    o[tid] = r;
}

// ============================================================
extern "C" void kernel_launch(void* const* d_in, const int* in_sizes, int n_in,
                              void* d_out, int out_size)
{
    const float* Q     = (const float*)d_in[0];
    const float* K     = (const float*)d_in[1];
    const float* V     = (const float*)d_in[2];
    const float* Wq    = (const float*)d_in[3];
    const float* bq    = (const float*)d_in[4];
    const float* Wk    = (const float*)d_in[5];
    const float* bk    = (const float*)d_in[6];
    const float* Wv    = (const float*)d_in[7];
    const float* bv    = (const float*)d_in[8];
    const float* Wo    = (const float*)d_in[9];
    const float* bo    = (const float*)d_in[10];
    const float* gamma = (const float*)d_in[11];
    const float* beta  = (const float*)d_in[12];

    float* out    = (float*)d_out;
    float* scores = out + OUT_OFF;

    bf16 *pah, *pal, *pwh, *pwl, *pch, *pcl;
    float *gy, *ge;
    cudaGetSymbolAddress((void**)&pah,  g_pah);
    cudaGetSymbolAddress((void**)&pal,  g_pal);
    cudaGetSymbolAddress((void**)&pwh,  g_pwh);
    cudaGetSymbolAddress((void**)&pwl,  g_pwl);
    cudaGetSymbolAddress((void**)&pch,  g_pch);
    cudaGetSymbolAddress((void**)&pcl,  g_pcl);
    cudaGetSymbolAddress((void**)&gy,   g_y);
    cudaGetSymbolAddress((void**)&ge,   g_e);

    static bool attr_set = false;
    if (!attr_set){
        cudaFuncSetAttribute(proj_kernel,   cudaFuncAttributeMaxDynamicSharedMemorySize, PR_SMEM);
        cudaFuncSetAttribute(scores_kernel, cudaFuncAttributeMaxDynamicSharedMemorySize, SC_SMEM);
        cudaFuncSetAttribute(av_kernel,     cudaFuncAttributeMaxDynamicSharedMemorySize, AV_SMEM);
        attr_set = true;
    }

    dim3 blk(256);

    // all 7 splits in one launch
    dim3 gSp(4096, 7);
    split_all<<<gSp, blk>>>(Q, K, V, Wq, Wk, Wv, Wo);

    // merged QKV projections
    dim3 gP3(8, 32, 3);
    proj_kernel<<<gP3, blk, PR_SMEM>>>(pah, pal, pwh, pwl,
                                       bq, bk, bv, nullptr, nullptr, 1);

    // scores -> E f32 (scratch) + partial row sums
    dim3 gSc(Sq/128, Sq/128, Bq*Hq);
    scores_kernel<<<gSc, blk, SC_SMEM>>>(ge);

    // av: read E scratch, write normalized P to d_out, PV mma
    dim3 gAv(Sq/64, Bq*Hq);     // (32, 32)
    av_kernel<<<gAv, blk, AV_SMEM>>>(ge, scores);

    // O projection + bias + residual -> g_y
    dim3 gP1(8, 32, 1);
    proj_kernel<<<gP1, blk, PR_SMEM>>>(pch, pcl, pwh + 3*(size_t)WN, pwl + 3*(size_t)WN,
                                       bo, bo, bo, Q, gy, 0);

    ln_kernel<<<(unsigned)Mq, blk>>>(gamma, beta, out);
}

// round 14
// speedup vs baseline: 1.0575x; 1.0014x over previous
#include <cuda_runtime.h>
#include <cuda_bf16.h>
#include <math.h>
#include <stdint.h>

#define Bq 2
#define Sq 2048
#define Dq 1024
#define Hq 16
#define DHq 64
#define Mq (Bq*Sq)
#define NELEM (Mq*Dq)
#define WN (Dq*Dq)
#define OUT_OFF ((size_t)Mq*Dq)

typedef __nv_bfloat16 bf16;
typedef __nv_bfloat162 bf162;

#define SWZ(x) ((x) ^ ((((uint32_t)(x))>>3)&0x70))

// ---------------- global scratch ----------------
__device__ __align__(16) bf16 g_pah[3][NELEM], g_pal[3][NELEM];
__device__ __align__(16) bf16 g_pwh[4][WN],    g_pwl[4][WN];
__device__ __align__(16) bf16 g_pch[NELEM],    g_pcl[NELEM];
__device__ __align__(16) bf16 g_qh[NELEM], g_ql[NELEM];
__device__ __align__(16) bf16 g_kh[NELEM], g_kl[NELEM];
__device__ __align__(16) bf16 g_vh[NELEM], g_vl[NELEM];
__device__ float g_y[NELEM];
__device__ float g_psum[(size_t)Bq*Hq*16*Sq];
__device__ __align__(16) float g_e[(size_t)Bq*Hq*Sq*Sq];

// ---------------- helpers ----------------
__device__ __forceinline__ uint32_t s2u(const void* p){ return (uint32_t)__cvta_generic_to_shared(p); }
__device__ __forceinline__ void cpa16(uint32_t s, const void* g){
    asm volatile("cp.async.cg.shared.global [%0], [%1], 16;\n" :: "r"(s), "l"(g));
}
__device__ __forceinline__ void cpcommit(){ asm volatile("cp.async.commit_group;\n" ::: "memory"); }
__device__ __forceinline__ void ldm4(uint32_t a, uint32_t&r0,uint32_t&r1,uint32_t&r2,uint32_t&r3){
    asm volatile("ldmatrix.sync.aligned.m8n8.x4.shared.b16 {%0,%1,%2,%3}, [%4];\n"
        : "=r"(r0),"=r"(r1),"=r"(r2),"=r"(r3) : "r"(a));
}
__device__ __forceinline__ void ldm4t(uint32_t a, uint32_t&r0,uint32_t&r1,uint32_t&r2,uint32_t&r3){
    asm volatile("ldmatrix.sync.aligned.m8n8.x4.trans.shared.b16 {%0,%1,%2,%3}, [%4];\n"
        : "=r"(r0),"=r"(r1),"=r"(r2),"=r"(r3) : "r"(a));
}
__device__ __forceinline__ void mma16(float* c, uint32_t a0,uint32_t a1,uint32_t a2,uint32_t a3,
                                      uint32_t b0,uint32_t b1){
    asm volatile("mma.sync.aligned.m16n8k16.row.col.f32.bf16.bf16.f32 "
        "{%0,%1,%2,%3}, {%4,%5,%6,%7}, {%8,%9}, {%0,%1,%2,%3};\n"
        : "+f"(c[0]),"+f"(c[1]),"+f"(c[2]),"+f"(c[3])
        : "r"(a0),"r"(a1),"r"(a2),"r"(a3),"r"(b0),"r"(b1));
}
__device__ __forceinline__ void split2(float x, bf16& h, bf16& l){
    h = __float2bfloat16(x);
    l = __float2bfloat16(x - __bfloat162float(h));
}
__device__ __forceinline__ void stcs4(float* p, float4 v){
    asm volatile("st.global.cs.v4.f32 [%0], {%1,%2,%3,%4};\n"
        :: "l"(p), "f"(v.x), "f"(v.y), "f"(v.z), "f"(v.w) : "memory");
}
__device__ __forceinline__ void stcs2(float* p, float2 v){
    asm volatile("st.global.cs.v2.f32 [%0], {%1,%2};\n"
        :: "l"(p), "f"(v.x), "f"(v.y) : "memory");
}

// ---- bulk TMA + mbarrier ----
__device__ __forceinline__ void bulk_ld(uint32_t dst, const void* src, uint32_t bytes, uint32_t mbar){
    asm volatile("cp.async.bulk.shared::cta.global.mbarrier::complete_tx::bytes [%0], [%1], %2, [%3];\n"
        :: "r"(dst), "l"(src), "r"(bytes), "r"(mbar) : "memory");
}
__device__ __forceinline__ void mbar_init(uint32_t mbar, uint32_t cnt){
    asm volatile("mbarrier.init.shared.b64 [%0], %1;\n" :: "r"(mbar), "r"(cnt) : "memory");
}
__device__ __forceinline__ void mbar_expect(uint32_t mbar, uint32_t tx){
    asm volatile("mbarrier.arrive.expect_tx.shared.b64 _, [%0], %1;\n" :: "r"(mbar), "r"(tx) : "memory");
}
__device__ __forceinline__ void mbar_wait(uint32_t mbar, uint32_t parity){
    asm volatile("{\n\t.reg .pred P;\n\t"
        "W%=:\n\t"
        "mbarrier.try_wait.parity.acquire.cta.shared::cta.b64 P, [%0], %1, 0x989680;\n\t"
        "@!P bra W%=;\n\t}\n"
        :: "r"(mbar), "r"(parity) : "memory");
}

// ---------------- split all 7 f32 matrices in ONE launch ----------------
__global__ void split_all(const float* __restrict__ Q, const float* __restrict__ K,
                          const float* __restrict__ V, const float* __restrict__ W0,
                          const float* __restrict__ W1, const float* __restrict__ W2,
                          const float* __restrict__ W3)
{
    const int y = blockIdx.y;
    const float* src;
    bf16 *th, *tl;
    int n4;
    if (y < 3){
        src = (y==0) ? Q : (y==1) ? K : V;
        th = g_pah[y]; tl = g_pal[y]; n4 = NELEM/4;
    } else {
        const int w = y - 3;
        src = (w==0) ? W0 : (w==1) ? W1 : (w==2) ? W2 : W3;
        th = g_pwh[w]; tl = g_pwl[w]; n4 = WN/4;
    }
    const int i = blockIdx.x*blockDim.x + threadIdx.x;
    if (i >= n4) return;
    const int r = i >> 8, c4 = (i & 255) << 2;
    float4 v = reinterpret_cast<const float4*>(src)[i];
    bf16 h0,l0,h1,l1,h2,l2,h3,l3;
    split2(v.x,h0,l0); split2(v.y,h1,l1); split2(v.z,h2,l2); split2(v.w,h3,l3);
    const size_t tile = (size_t)((r>>7)*16 + (c4>>6)) * 16384;
    const uint32_t off = SWZ(((r&127)<<7) + ((c4&63)<<1));
    char* dh = (char*)th + tile + off;
    char* dl = (char*)tl + tile + off;
    *reinterpret_cast<bf162*>(dh)   = __halves2bfloat162(h0,h1);
    *reinterpret_cast<bf162*>(dh+4) = __halves2bfloat162(h2,h3);
    *reinterpret_cast<bf162*>(dl)   = __halves2bfloat162(l0,l1);
    *reinterpret_cast<bf162*>(dl+4) = __halves2bfloat162(l2,l3);
}

// ============================================================
// Projection GEMM (NT, mma.sync, bulk-TMA staged)
// qkv==1: z=0 q (tile-major, 3-term), z=1 k (tile-major, 3-term),
//         z=2 v (row-major, 2-term)
// qkv==0: O projection, f32 + bias + resid (2-term)
// ============================================================
#define PR_STAGE 65536
#define PR_SMEM  (128 + 2*PR_STAGE)

__global__ __launch_bounds__(256,1) void proj_kernel(
    const bf16* __restrict__ Ahg0, const bf16* __restrict__ Alg0,
    const bf16* __restrict__ Bhg0, const bf16* __restrict__ Blg0,
    const float* __restrict__ bias0, const float* __restrict__ bias1,
    const float* __restrict__ bias2, const float* __restrict__ resid,
    float* __restrict__ outf, int qkv)
{
    extern __shared__ __align__(128) char sm_[];
    const int tid = threadIdx.x, lane = tid&31, warp = tid>>5;
    const int n0 = blockIdx.x, m0 = blockIdx.y, z = blockIdx.z;
    const bf16* Ahg = Ahg0 + (size_t)z*NELEM;
    const bf16* Alg = Alg0 + (size_t)z*NELEM;
    const bf16* Bhg = Bhg0 + (size_t)z*WN;
    const bf16* Blg = Blg0 + (size_t)z*WN;
    const float* bias = (z==0) ? bias0 : (z==1) ? bias1 : bias2;
    const bool three = qkv && (z < 2);    // Q/K: 3-term; V and O: 2-term
    const uint32_t sb = s2u(sm_);
    const uint32_t dat = sb + 128;

    if (tid == 0){
        mbar_init(sb+0, 1);
        mbar_init(sb+8, 1);
#pragma unroll
        for (int p = 0; p < 2; p++){
            const uint32_t mb = sb + p*8;
            const uint32_t buf = dat + p*PR_STAGE;
            mbar_expect(mb, PR_STAGE);
            bulk_ld(buf,        (const char*)Ahg + (size_t)(m0*16+p)*16384, 16384, mb);
            bulk_ld(buf+16384,  (const char*)Alg + (size_t)(m0*16+p)*16384, 16384, mb);
            bulk_ld(buf+32768,  (const char*)Bhg + (size_t)(n0*16+p)*16384, 16384, mb);
            bulk_ld(buf+49152,  (const char*)Blg + (size_t)(n0*16+p)*16384, 16384, mb);
        }
    }
    __syncthreads();

    const int wm = (warp>>2)*64, wn = (warp&3)*32;
    float acc[4][4][4] = {};

    for (int kt = 0; kt < 16; kt++){
        const int b = kt & 1;
        mbar_wait(sb + b*8, (kt>>1)&1);
        const uint32_t buf = dat + b*PR_STAGE;
#pragma unroll
        for (int ks = 0; ks < 4; ks++){
            uint32_t bhf[4][2], blf[4][2];
#pragma unroll
            for (int p = 0; p < 2; p++){
                const uint32_t roff = (uint32_t)(wn + p*16 + (lane&7) + ((lane>>4)&1)*8)*128
                                      + ks*32 + ((lane>>3)&1)*16;
                ldm4(buf + 32768 + SWZ(roff), bhf[2*p][0], bhf[2*p][1], bhf[2*p+1][0], bhf[2*p+1][1]);
                ldm4(buf + 49152 + SWZ(roff), blf[2*p][0], blf[2*p][1], blf[2*p+1][0], blf[2*p+1][1]);
            }
#pragma unroll
            for (int mi = 0; mi < 4; mi++){
                const uint32_t roff = (uint32_t)(wm + mi*16 + (lane&15))*128
                                      + ks*32 + ((lane>>4)&1)*16;
                uint32_t a0,a1,a2,a3, l0,l1,l2,l3;
                ldm4(buf +         SWZ(roff), a0,a1,a2,a3);
                ldm4(buf + 16384 + SWZ(roff), l0,l1,l2,l3);
#pragma unroll
                for (int ni = 0; ni < 4; ni++){
                    mma16(acc[mi][ni], a0,a1,a2,a3, bhf[ni][0], bhf[ni][1]);
                    mma16(acc[mi][ni], a0,a1,a2,a3, blf[ni][0], blf[ni][1]);
                    if (three)
                        mma16(acc[mi][ni], l0,l1,l2,l3, bhf[ni][0], bhf[ni][1]);
                }
            }
        }
        __syncthreads();
        if (tid == 0 && kt+2 < 16){
            const uint32_t mb = sb + b*8;
            mbar_expect(mb, PR_STAGE);
            bulk_ld(buf,        (const char*)Ahg + (size_t)(m0*16+kt+2)*16384, 16384, mb);
            bulk_ld(buf+16384,  (const char*)Alg + (size_t)(m0*16+kt+2)*16384, 16384, mb);
            bulk_ld(buf+32768,  (const char*)Bhg + (size_t)(n0*16+kt+2)*16384, 16384, mb);
            bulk_ld(buf+49152,  (const char*)Blg + (size_t)(n0*16+kt+2)*16384, 16384, mb);
        }
    }

    const int bm = m0*128, bn = n0*128;
    const int g = lane>>2, tg = lane&3;
    bf16* outh = (z==0) ? g_qh : (z==1) ? g_kh : g_vh;
    bf16* outl = (z==0) ? g_ql : (z==1) ? g_kl : g_vl;
    const int mode = qkv ? ((z==2) ? 0 : 1) : 2;
#pragma unroll
    for (int mi=0; mi<4; mi++)
#pragma unroll
    for (int ni=0; ni<4; ni++){
        const int r0 = bm+wm+mi*16+g;
        const int c  = bn+wn+ni*8+tg*2;
        const float2 bv = *reinterpret_cast<const float2*>(&bias[c]);
        const float x0=acc[mi][ni][0]+bv.x, x1=acc[mi][ni][1]+bv.y;
        const float x2=acc[mi][ni][2]+bv.x, x3=acc[mi][ni][3]+bv.y;
        if (mode == 2){
            const float2 q0 = *reinterpret_cast<const float2*>(&resid[(size_t)r0*Dq + c]);
            const float2 q1 = *reinterpret_cast<const float2*>(&resid[(size_t)(r0+8)*Dq + c]);
            *reinterpret_cast<float2*>(&outf[(size_t)r0*Dq+c])     = make_float2(x0+q0.x, x1+q0.y);
            *reinterpret_cast<float2*>(&outf[(size_t)(r0+8)*Dq+c]) = make_float2(x2+q1.x, x3+q1.y);
        } else if (mode == 1){
            bf16 h0,l0,h1,l1;
#pragma unroll
            for (int hh = 0; hh < 2; hh++){
                const int rr = r0 + hh*8;
                const size_t tb = ((size_t)(rr>>7)*16 + (c>>6)) * 16384;
                const uint32_t off = SWZ(((rr&127)<<7) + ((c&63)<<1));
                const float y0 = hh ? x2 : x0;
                const float y1 = hh ? x3 : x1;
                split2(y0,h0,l0); split2(y1,h1,l1);
                *reinterpret_cast<bf162*>((char*)outh + tb + off) = __halves2bfloat162(h0,h1);
                *reinterpret_cast<bf162*>((char*)outl + tb + off) = __halves2bfloat162(l0,l1);
            }
        } else {
            bf16 h0,l0,h1,l1;
            split2(x0,h0,l0); split2(x1,h1,l1);
            *reinterpret_cast<bf162*>(&outh[(size_t)r0*Dq+c]) = __halves2bfloat162(h0,h1);
            *reinterpret_cast<bf162*>(&outl[(size_t)r0*Dq+c]) = __halves2bfloat162(l0,l1);
            split2(x2,h0,l0); split2(x3,h1,l1);
            *reinterpret_cast<bf162*>(&outh[(size_t)(r0+8)*Dq+c]) = __halves2bfloat162(h0,h1);
            *reinterpret_cast<bf162*>(&outl[(size_t)(r0+8)*Dq+c]) = __halves2bfloat162(l0,l1);
        }
    }
}

// ============================================================
// Scores: E -> g_e scratch via streaming stores + partial row sums
// ============================================================
#define SC_SMEM (128 + 65536)

__global__ __launch_bounds__(256) void scores_kernel(float* __restrict__ escr)
{
    extern __shared__ __align__(128) char sm_[];
    const int bh = blockIdx.z, b = bh>>4, h = bh&15;
    const int tid = threadIdx.x, lane = tid&31, warp = tid>>5;
    const int bm = blockIdx.y*128, bn = blockIdx.x*128;
    const uint32_t sb = s2u(sm_);
    const uint32_t dat = sb + 128;

    const size_t atile = ((size_t)(b*16 + blockIdx.y)*16 + h) * 16384;
    const size_t btile = ((size_t)(b*16 + blockIdx.x)*16 + h) * 16384;

    if (tid == 0){
        mbar_init(sb, 1);
    }
    __syncthreads();
    if (tid == 0){
        mbar_expect(sb, 65536);
        bulk_ld(dat,        (const char*)g_qh + atile, 16384, sb);
        bulk_ld(dat+16384,  (const char*)g_ql + atile, 16384, sb);
        bulk_ld(dat+32768,  (const char*)g_kh + btile, 16384, sb);
        bulk_ld(dat+49152,  (const char*)g_kl + btile, 16384, sb);
    }

    const int wm = (warp>>2)*64, wn = (warp&3)*32;
    float acc[4][4][4] = {};

    mbar_wait(sb, 0);

#pragma unroll
    for (int ks = 0; ks < 4; ks++){
        uint32_t bhf[4][2], blf[4][2];
#pragma unroll
        for (int p = 0; p < 2; p++){
            const uint32_t roff = (uint32_t)(wn + p*16 + (lane&7) + ((lane>>4)&1)*8)*128
                                  + ks*32 + ((lane>>3)&1)*16;
            ldm4(dat + 32768 + SWZ(roff), bhf[2*p][0], bhf[2*p][1], bhf[2*p+1][0], bhf[2*p+1][1]);
            ldm4(dat + 49152 + SWZ(roff), blf[2*p][0], blf[2*p][1], blf[2*p+1][0], blf[2*p+1][1]);
        }
#pragma unroll
        for (int mi = 0; mi < 4; mi++){
            const uint32_t roff = (uint32_t)(wm + mi*16 + (lane&15))*128
                                  + ks*32 + ((lane>>4)&1)*16;
            uint32_t a0,a1,a2,a3, l0,l1,l2,l3;
            ldm4(dat +         SWZ(roff), a0,a1,a2,a3);
            ldm4(dat + 16384 + SWZ(roff), l0,l1,l2,l3);
#pragma unroll
            for (int ni = 0; ni < 4; ni++){
                mma16(acc[mi][ni], a0,a1,a2,a3, bhf[ni][0], bhf[ni][1]);
                mma16(acc[mi][ni], a0,a1,a2,a3, blf[ni][0], blf[ni][1]);
                mma16(acc[mi][ni], l0,l1,l2,l3, bhf[ni][0], bhf[ni][1]);
            }
        }
    }

    __shared__ float psum[128][4];
    float* C = escr + (size_t)bh*Sq*Sq;
    const int g=lane>>2, tg=lane&3;
    const int wnidx = warp & 3;
#pragma unroll
    for (int mi=0; mi<4; mi++){
        float s0 = 0.f, s1 = 0.f;
#pragma unroll
        for (int ni=0; ni<4; ni++){
            const int r0 = bm+wm+mi*16+g;
            const int c  = bn+wn+ni*8+tg*2;
            const float e0 = __expf(acc[mi][ni][0]*0.125f);
            const float e1 = __expf(acc[mi][ni][1]*0.125f);
            const float e2 = __expf(acc[mi][ni][2]*0.125f);
            const float e3 = __expf(acc[mi][ni][3]*0.125f);
            stcs2(&C[(size_t)r0*Sq+c],     make_float2(e0, e1));
            stcs2(&C[(size_t)(r0+8)*Sq+c], make_float2(e2, e3));
            s0 += e0 + e1;
            s1 += e2 + e3;
        }
        s0 += __shfl_xor_sync(0xffffffffu, s0, 1);
        s0 += __shfl_xor_sync(0xffffffffu, s0, 2);
        s1 += __shfl_xor_sync(0xffffffffu, s1, 1);
        s1 += __shfl_xor_sync(0xffffffffu, s1, 2);
        if (tg == 0){
            psum[wm+mi*16+g][wnidx]   = s0;
            psum[wm+mi*16+g+8][wnidx] = s1;
        }
    }
    __syncthreads();
    if (tid < 128){
        const float t = psum[tid][0] + psum[tid][1] + psum[tid][2] + psum[tid][3];
        g_psum[((size_t)bh*16 + blockIdx.x)*Sq + bm + tid] = t;
    }
}

// ============================================================
// av v3: 64-row q tiles, 5-stage cp.async ring, wait_group 3,
// streaming P stores.
// ============================================================
#define AV_PP    144
#define AV_PSTG  (64*AV_PP)
#define AV_VSTG  (32*144)
#define AV_STG   (AV_PSTG + 2*AV_VSTG)
#define AV_NST   5
#define AV_EP    80
#define AV_EH    (64*AV_EP)
#define AV_SMEM  (512 + AV_NST*AV_STG + 2*AV_EH)

__global__ __launch_bounds__(256,2) void av_kernel(const float* __restrict__ escr,
                                                   float* __restrict__ scores)
{
    extern __shared__ __align__(128) char sm_[];
    const int qt = blockIdx.x, bh = blockIdx.y, b = bh>>4, h = bh&15;
    const int bm = qt*64;
    const int tid = threadIdx.x, lane = tid&31, warp = tid>>5;
    const float* E = escr + (size_t)bh*Sq*Sq;
    float* P = scores + (size_t)bh*Sq*Sq;
    const bf16* Vhg = g_vh + (size_t)b*Sq*Dq + h*DHq;
    const bf16* Vlg = g_vl + (size_t)b*Sq*Dq + h*DHq;

    float* invs = reinterpret_cast<float*>(sm_);
    const uint32_t su = s2u(sm_ + 512);
    const uint32_t eu = su + AV_NST*AV_STG;

    if (tid < 64){
        float s = 0.f;
#pragma unroll
        for (int t = 0; t < 16; t++)
            s += g_psum[((size_t)bh*16 + t)*Sq + bm + tid];
        invs[tid] = 1.0f / s;
    }

    auto fill = [&](int p, int kt){
        const int k0 = kt*32;
        const uint32_t sbase = su + (uint32_t)p*AV_STG;
#pragma unroll
        for (int c = 0; c < 2; c++){
            const int ch = tid + c*256;
            const int rr = ch >> 3, cc = ch & 7;
            cpa16(sbase + (uint32_t)(rr*AV_PP + cc*16),
                  &E[(size_t)(bm + rr)*Sq + k0 + cc*4]);
        }
#pragma unroll
        for (int c = 0; c < 2; c++){
            const int ch = tid + c*256;
            const int part = ch >> 8, idx = ch & 255;
            const int vr = idx >> 3, vc = idx & 7;
            const bf16* src = part ? Vlg : Vhg;
            cpa16(sbase + AV_PSTG + (uint32_t)(part*AV_VSTG + vr*144 + vc*16),
                  src + (size_t)(k0 + vr)*Dq + vc*8);
        }
        cpcommit();
    };

    fill(0,0); fill(1,1); fill(2,2); fill(3,3);
    __syncthreads();

    const int pr = tid>>2, pc0 = (tid&3)*8;
    const float inv = invs[pr];
    const int wm = (warp>>1)*16, wn = (warp&1)*32;

    float acc[4][4] = {};

    for (int kt = 0; kt < 64; kt++){
        const int s = kt % AV_NST;
        asm volatile("cp.async.wait_group 3;\n" ::: "memory");
        __syncthreads();

        if (kt+4 < 64) fill((kt+4)%AV_NST, kt+4);

        {
            const char* ps = sm_ + 512 + s*AV_STG;
            char* EhB = sm_ + 512 + AV_NST*AV_STG;
#pragma unroll
            for (int j = 0; j < 2; j++){
                const int c = pc0 + j*4;
                float4 v = *reinterpret_cast<const float4*>(ps + pr*AV_PP + c*4);
                v.x *= inv; v.y *= inv; v.z *= inv; v.w *= inv;
                stcs4(&P[(size_t)(bm + pr)*Sq + kt*32 + c], v);
                bf16 h0,l0,h1,l1,h2,l2,h3,l3;
                split2(v.x,h0,l0); split2(v.y,h1,l1); split2(v.z,h2,l2); split2(v.w,h3,l3);
                char* eh = EhB + pr*AV_EP + c*2;
                *reinterpret_cast<bf162*>(eh)           = __halves2bfloat162(h0,h1);
                *reinterpret_cast<bf162*>(eh+4)         = __halves2bfloat162(h2,h3);
                *reinterpret_cast<bf162*>(eh + AV_EH)   = __halves2bfloat162(l0,l1);
                *reinterpret_cast<bf162*>(eh + AV_EH+4) = __halves2bfloat162(l2,l3);
            }
        }
        __syncthreads();

        const uint32_t stv = su + (uint32_t)s*AV_STG + AV_PSTG;
#pragma unroll
        for (int ks = 0; ks < 2; ks++){
            uint32_t bhf[4][2], blf[4][2];
#pragma unroll
            for (int p = 0; p < 2; p++){
                const uint32_t ro = (uint32_t)((ks*16 + ((lane>>3)&1)*8 + (lane&7))*144
                                    + (wn + p*16 + ((lane>>4)&1)*8)*2);
                ldm4t(stv + ro,           bhf[2*p][0], bhf[2*p][1], bhf[2*p+1][0], bhf[2*p+1][1]);
                ldm4t(stv + AV_VSTG + ro, blf[2*p][0], blf[2*p][1], blf[2*p+1][0], blf[2*p+1][1]);
            }
            const uint32_t ao = (uint32_t)((wm + (lane&15))*AV_EP
                                + ks*32 + ((lane>>4)&1)*16);
            uint32_t a0,a1,a2,a3, l0,l1,l2,l3;
            ldm4(eu + ao,         a0,a1,a2,a3);
            ldm4(eu + AV_EH + ao, l0,l1,l2,l3);
#pragma unroll
            for (int ni = 0; ni < 4; ni++){
                mma16(acc[ni], a0,a1,a2,a3, bhf[ni][0], bhf[ni][1]);
                mma16(acc[ni], a0,a1,a2,a3, blf[ni][0], blf[ni][1]);
                mma16(acc[ni], l0,l1,l2,l3, bhf[ni][0], bhf[ni][1]);
            }
        }
    }

    const int g = lane>>2, tg = lane&3;
#pragma unroll
    for (int ni = 0; ni < 4; ni++){
        const int r0 = bm + wm + g;
        const int c  = wn + ni*8 + tg*2;
#pragma unroll
        for (int hh = 0; hh < 2; hh++){
            const int grow = b*Sq + r0 + hh*8;
            const size_t tb = ((size_t)((grow>>7)*16 + h)) * 16384;
            const uint32_t off = SWZ(((grow&127)<<7) + (c<<1));
            const float x0 = acc[ni][hh*2+0];
            const float x1 = acc[ni][hh*2+1];
            bf16 h0,l0,h1,l1;
            split2(x0,h0,l0); split2(x1,h1,l1);
            *reinterpret_cast<bf162*>((char*)g_pch + tb + off) = __halves2bfloat162(h0,h1);
            *reinterpret_cast<bf162*>((char*)g_pcl + tb + off) = __halves2bfloat162(l0,l1);
        }
    }
}

// ============================================================
// LayerNorm per row of g_y -> d_out
// ============================================================
__global__ void ln_kernel(const float* __restrict__ gamma,
                          const float* __restrict__ beta,
                          float* __restrict__ out)
{
    const size_t row = blockIdx.x;
    const float4* y = reinterpret_cast<const float4*>(g_y + row * (size_t)Dq);
    float4* o = reinterpret_cast<float4*>(out + row * (size_t)Dq);
    const int tid = threadIdx.x;
    __shared__ float sm[8], sm2[8];

    float4 v = y[tid];
    float s  = v.x + v.y + v.z + v.w;
    float s2 = v.x*v.x + v.y*v.y + v.z*v.z + v.w*v.w;
#pragma unroll
    for (int o2 = 16; o2 > 0; o2 >>= 1) {
        s  += __shfl_xor_sync(0xffffffffu, s,  o2);
        s2 += __shfl_xor_sync(0xffffffffu, s2, o2);
    }
    if ((tid & 31) == 0) { sm[tid>>5] = s; sm2[tid>>5] = s2; }
    __syncthreads();
    float ts = 0.f, ts2 = 0.f;
#pragma unroll
    for (int w = 0; w < 8; w++) { ts += sm[w]; ts2 += sm2[w]; }
    const float mean = ts * (1.0f/Dq);
    const float var  = ts2 * (1.0f/Dq) - mean*mean;
    const float rstd = rsqrtf(var + 1e-6f);

    const float4 gg = reinterpret_cast<const float4*>(gamma)[tid];
    const float4 bb = reinterpret_cast<const float4*>(beta)[tid];
    float4 r;
    r.x = (v.x - mean) * rstd * gg.x + bb.x;
    r.y = (v.y - mean) * rstd * gg.y + bb.y;
    r.z = (v.z - mean) * rstd * gg.z + bb.z;
    r.w = (v.w - mean) * rstd * gg.w + bb.w;
    o[tid] = r;
}

// ============================================================
extern "C" void kernel_launch(void* const* d_in, const int* in_sizes, int n_in,
                              void* d_out, int out_size)
{
    const float* Q     = (const float*)d_in[0];
    const float* K     = (const float*)d_in[1];
    const float* V     = (const float*)d_in[2];
    const float* Wq    = (const float*)d_in[3];
    const float* bq    = (const float*)d_in[4];
    const float* Wk    = (const float*)d_in[5];
    const float* bk    = (const float*)d_in[6];
    const float* Wv    = (const float*)d_in[7];
    const float* bv    = (const float*)d_in[8];
    const float* Wo    = (const float*)d_in[9];
    const float* bo    = (const float*)d_in[10];
    const float* gamma = (const float*)d_in[11];
    const float* beta  = (const float*)d_in[12];

    float* out    = (float*)d_out;
    float* scores = out + OUT_OFF;

    bf16 *pah, *pal, *pwh, *pwl, *pch, *pcl;
    float *gy, *ge;
    cudaGetSymbolAddress((void**)&pah,  g_pah);
    cudaGetSymbolAddress((void**)&pal,  g_pal);
    cudaGetSymbolAddress((void**)&pwh,  g_pwh);
    cudaGetSymbolAddress((void**)&pwl,  g_pwl);
    cudaGetSymbolAddress((void**)&pch,  g_pch);
    cudaGetSymbolAddress((void**)&pcl,  g_pcl);
    cudaGetSymbolAddress((void**)&gy,   g_y);
    cudaGetSymbolAddress((void**)&ge,   g_e);

    static bool attr_set = false;
    if (!attr_set){
        cudaFuncSetAttribute(proj_kernel,   cudaFuncAttributeMaxDynamicSharedMemorySize, PR_SMEM);
        cudaFuncSetAttribute(scores_kernel, cudaFuncAttributeMaxDynamicSharedMemorySize, SC_SMEM);
        cudaFuncSetAttribute(av_kernel,     cudaFuncAttributeMaxDynamicSharedMemorySize, AV_SMEM);
        attr_set = true;
    }

    dim3 blk(256);

    dim3 gSp(4096, 7);
    split_all<<<gSp, blk>>>(Q, K, V, Wq, Wk, Wv, Wo);

    dim3 gP3(8, 32, 3);
    proj_kernel<<<gP3, blk, PR_SMEM>>>(pah, pal, pwh, pwl,
                                       bq, bk, bv, nullptr, nullptr, 1);

    dim3 gSc(Sq/128, Sq/128, Bq*Hq);
    scores_kernel<<<gSc, blk, SC_SMEM>>>(ge);

    dim3 gAv(Sq/64, Bq*Hq);
    av_kernel<<<gAv, blk, AV_SMEM>>>(ge, scores);

    dim3 gP1(8, 32, 1);
    proj_kernel<<<gP1, blk, PR_SMEM>>>(pch, pcl, pwh + 3*(size_t)WN, pwl + 3*(size_t)WN,
                                       bo, bo, bo, Q, gy, 0);

    ln_kernel<<<(unsigned)Mq, blk>>>(gamma, beta, out);
}

// round 16
// speedup vs baseline: 1.1062x; 1.0461x over previous
#include <cuda_runtime.h>
#include <cuda_bf16.h>
#include <cuda_fp16.h>
#include <math.h>
#include <stdint.h>

#define Bq 2
#define Sq 2048
#define Dq 1024
#define Hq 16
#define DHq 64
#define Mq (Bq*Sq)
#define NELEM (Mq*Dq)
#define WN (Dq*Dq)
#define OUT_OFF ((size_t)Mq*Dq)

typedef __nv_bfloat16 bf16;
typedef __nv_bfloat162 bf162;

#define SWZ(x) ((x) ^ ((((uint32_t)(x))>>3)&0x70))

// ---------------- global scratch ----------------
__device__ __align__(16) bf16 g_pah[3][NELEM], g_pal[3][NELEM];
__device__ __align__(16) bf16 g_pwh[4][WN],    g_pwl[4][WN];
__device__ __align__(16) bf16 g_pch[NELEM],    g_pcl[NELEM];
__device__ __align__(16) bf16 g_qh[NELEM], g_ql[NELEM];
__device__ __align__(16) bf16 g_kh[NELEM], g_kl[NELEM];
__device__ __align__(16) bf16 g_vh[NELEM], g_vl[NELEM];
__device__ float g_y[NELEM];
__device__ float g_psum[(size_t)Bq*Hq*16*Sq];
// E = exp(S/8) scratch, HALF precision (halves the stream)
__device__ __align__(16) __half g_e[(size_t)Bq*Hq*Sq*Sq];

// ---------------- helpers ----------------
__device__ __forceinline__ uint32_t s2u(const void* p){ return (uint32_t)__cvta_generic_to_shared(p); }
__device__ __forceinline__ void cpa16(uint32_t s, const void* g){
    asm volatile("cp.async.cg.shared.global [%0], [%1], 16;\n" :: "r"(s), "l"(g));
}
__device__ __forceinline__ void cpcommit(){ asm volatile("cp.async.commit_group;\n" ::: "memory"); }
__device__ __forceinline__ void ldm4(uint32_t a, uint32_t&r0,uint32_t&r1,uint32_t&r2,uint32_t&r3){
    asm volatile("ldmatrix.sync.aligned.m8n8.x4.shared.b16 {%0,%1,%2,%3}, [%4];\n"
        : "=r"(r0),"=r"(r1),"=r"(r2),"=r"(r3) : "r"(a));
}
__device__ __forceinline__ void ldm4t(uint32_t a, uint32_t&r0,uint32_t&r1,uint32_t&r2,uint32_t&r3){
    asm volatile("ldmatrix.sync.aligned.m8n8.x4.trans.shared.b16 {%0,%1,%2,%3}, [%4];\n"
        : "=r"(r0),"=r"(r1),"=r"(r2),"=r"(r3) : "r"(a));
}
__device__ __forceinline__ void mma16(float* c, uint32_t a0,uint32_t a1,uint32_t a2,uint32_t a3,
                                      uint32_t b0,uint32_t b1){
    asm volatile("mma.sync.aligned.m16n8k16.row.col.f32.bf16.bf16.f32 "
        "{%0,%1,%2,%3}, {%4,%5,%6,%7}, {%8,%9}, {%0,%1,%2,%3};\n"
        : "+f"(c[0]),"+f"(c[1]),"+f"(c[2]),"+f"(c[3])
        : "r"(a0),"r"(a1),"r"(a2),"r"(a3),"r"(b0),"r"(b1));
}
__device__ __forceinline__ void split2(float x, bf16& h, bf16& l){
    h = __float2bfloat16(x);
    l = __float2bfloat16(x - __bfloat162float(h));
}
__device__ __forceinline__ void stcs4(float* p, float4 v){
    asm volatile("st.global.cs.v4.f32 [%0], {%1,%2,%3,%4};\n"
        :: "l"(p), "f"(v.x), "f"(v.y), "f"(v.z), "f"(v.w) : "memory");
}
__device__ __forceinline__ void stcsh2(__half* p, __half2 v){
    asm volatile("st.global.cs.b32 [%0], %1;\n"
        :: "l"(p), "r"(*reinterpret_cast<uint32_t*>(&v)) : "memory");
}

// ---- bulk TMA + mbarrier ----
__device__ __forceinline__ void bulk_ld(uint32_t dst, const void* src, uint32_t bytes, uint32_t mbar){
    asm volatile("cp.async.bulk.shared::cta.global.mbarrier::complete_tx::bytes [%0], [%1], %2, [%3];\n"
        :: "r"(dst), "l"(src), "r"(bytes), "r"(mbar) : "memory");
}
__device__ __forceinline__ void mbar_init(uint32_t mbar, uint32_t cnt){
    asm volatile("mbarrier.init.shared.b64 [%0], %1;\n" :: "r"(mbar), "r"(cnt) : "memory");
}
__device__ __forceinline__ void mbar_expect(uint32_t mbar, uint32_t tx){
    asm volatile("mbarrier.arrive.expect_tx.shared.b64 _, [%0], %1;\n" :: "r"(mbar), "r"(tx) : "memory");
}
__device__ __forceinline__ void mbar_wait(uint32_t mbar, uint32_t parity){
    asm volatile("{\n\t.reg .pred P;\n\t"
        "W%=:\n\t"
        "mbarrier.try_wait.parity.acquire.cta.shared::cta.b64 P, [%0], %1, 0x989680;\n\t"
        "@!P bra W%=;\n\t}\n"
        :: "r"(mbar), "r"(parity) : "memory");
}

// ---------------- split all 7 f32 matrices in ONE launch ----------------
__global__ void split_all(const float* __restrict__ Q, const float* __restrict__ K,
                          const float* __restrict__ V, const float* __restrict__ W0,
                          const float* __restrict__ W1, const float* __restrict__ W2,
                          const float* __restrict__ W3)
{
    const int y = blockIdx.y;
    const float* src;
    bf16 *th, *tl;
    int n4;
    if (y < 3){
        src = (y==0) ? Q : (y==1) ? K : V;
        th = g_pah[y]; tl = g_pal[y]; n4 = NELEM/4;
    } else {
        const int w = y - 3;
        src = (w==0) ? W0 : (w==1) ? W1 : (w==2) ? W2 : W3;
        th = g_pwh[w]; tl = g_pwl[w]; n4 = WN/4;
    }
    const int i = blockIdx.x*blockDim.x + threadIdx.x;
    if (i >= n4) return;
    const int r = i >> 8, c4 = (i & 255) << 2;
    float4 v = reinterpret_cast<const float4*>(src)[i];
    bf16 h0,l0,h1,l1,h2,l2,h3,l3;
    split2(v.x,h0,l0); split2(v.y,h1,l1); split2(v.z,h2,l2); split2(v.w,h3,l3);
    const size_t tile = (size_t)((r>>7)*16 + (c4>>6)) * 16384;
    const uint32_t off = SWZ(((r&127)<<7) + ((c4&63)<<1));
    char* dh = (char*)th + tile + off;
    char* dl = (char*)tl + tile + off;
    *reinterpret_cast<bf162*>(dh)   = __halves2bfloat162(h0,h1);
    *reinterpret_cast<bf162*>(dh+4) = __halves2bfloat162(h2,h3);
    *reinterpret_cast<bf162*>(dl)   = __halves2bfloat162(l0,l1);
    *reinterpret_cast<bf162*>(dl+4) = __halves2bfloat162(l2,l3);
}

// ============================================================
// Projection GEMM (NT, mma.sync, bulk-TMA, 2-stage — known good)
// qkv==1: z=0 q (tile-major), z=1 k (tile-major), z=2 v (row-major)
// qkv==0: O projection, f32 + bias + resid
// All 3-term.
// ============================================================
#define PR_STAGE 65536
#define PR_SMEM  (128 + 2*PR_STAGE)

__global__ __launch_bounds__(256,1) void proj_kernel(
    const bf16* __restrict__ Ahg0, const bf16* __restrict__ Alg0,
    const bf16* __restrict__ Bhg0, const bf16* __restrict__ Blg0,
    const float* __restrict__ bias0, const float* __restrict__ bias1,
    const float* __restrict__ bias2, const float* __restrict__ resid,
    float* __restrict__ outf, int qkv)
{
    extern __shared__ __align__(128) char sm_[];
    const int tid = threadIdx.x, lane = tid&31, warp = tid>>5;
    const int n0 = blockIdx.x, m0 = blockIdx.y, z = blockIdx.z;
    const bf16* Ahg = Ahg0 + (size_t)z*NELEM;
    const bf16* Alg = Alg0 + (size_t)z*NELEM;
    const bf16* Bhg = Bhg0 + (size_t)z*WN;
    const bf16* Blg = Blg0 + (size_t)z*WN;
    const float* bias = (z==0) ? bias0 : (z==1) ? bias1 : bias2;
    const uint32_t sb = s2u(sm_);
    const uint32_t dat = sb + 128;

    if (tid == 0){
        mbar_init(sb+0, 1);
        mbar_init(sb+8, 1);
#pragma unroll
        for (int p = 0; p < 2; p++){
            const uint32_t mb = sb + p*8;
            const uint32_t buf = dat + p*PR_STAGE;
            mbar_expect(mb, PR_STAGE);
            bulk_ld(buf,        (const char*)Ahg + (size_t)(m0*16+p)*16384, 16384, mb);
            bulk_ld(buf+16384,  (const char*)Alg + (size_t)(m0*16+p)*16384, 16384, mb);
            bulk_ld(buf+32768,  (const char*)Bhg + (size_t)(n0*16+p)*16384, 16384, mb);
            bulk_ld(buf+49152,  (const char*)Blg + (size_t)(n0*16+p)*16384, 16384, mb);
        }
    }
    __syncthreads();

    const int wm = (warp>>2)*64, wn = (warp&3)*32;
    float acc[4][4][4] = {};

    for (int kt = 0; kt < 16; kt++){
        const int b = kt & 1;
        mbar_wait(sb + b*8, (kt>>1)&1);
        const uint32_t buf = dat + b*PR_STAGE;
#pragma unroll
        for (int ks = 0; ks < 4; ks++){
            uint32_t bhf[4][2], blf[4][2];
#pragma unroll
            for (int p = 0; p < 2; p++){
                const uint32_t roff = (uint32_t)(wn + p*16 + (lane&7) + ((lane>>4)&1)*8)*128
                                      + ks*32 + ((lane>>3)&1)*16;
                ldm4(buf + 32768 + SWZ(roff), bhf[2*p][0], bhf[2*p][1], bhf[2*p+1][0], bhf[2*p+1][1]);
                ldm4(buf + 49152 + SWZ(roff), blf[2*p][0], blf[2*p][1], blf[2*p+1][0], blf[2*p+1][1]);
            }
#pragma unroll
            for (int mi = 0; mi < 4; mi++){
                const uint32_t roff = (uint32_t)(wm + mi*16 + (lane&15))*128
                                      + ks*32 + ((lane>>4)&1)*16;
                uint32_t a0,a1,a2,a3, l0,l1,l2,l3;
                ldm4(buf +         SWZ(roff), a0,a1,a2,a3);
                ldm4(buf + 16384 + SWZ(roff), l0,l1,l2,l3);
#pragma unroll
                for (int ni = 0; ni < 4; ni++){
                    mma16(acc[mi][ni], a0,a1,a2,a3, bhf[ni][0], bhf[ni][1]);
                    mma16(acc[mi][ni], a0,a1,a2,a3, blf[ni][0], blf[ni][1]);
                    mma16(acc[mi][ni], l0,l1,l2,l3, bhf[ni][0], bhf[ni][1]);
                }
            }
        }
        __syncthreads();
        if (tid == 0 && kt+2 < 16){
            const uint32_t mb = sb + b*8;
            mbar_expect(mb, PR_STAGE);
            bulk_ld(buf,        (const char*)Ahg + (size_t)(m0*16+kt+2)*16384, 16384, mb);
            bulk_ld(buf+16384,  (const char*)Alg + (size_t)(m0*16+kt+2)*16384, 16384, mb);
            bulk_ld(buf+32768,  (const char*)Bhg + (size_t)(n0*16+kt+2)*16384, 16384, mb);
            bulk_ld(buf+49152,  (const char*)Blg + (size_t)(n0*16+kt+2)*16384, 16384, mb);
        }
    }

    const int bm = m0*128, bn = n0*128;
    const int g = lane>>2, tg = lane&3;
    bf16* outh = (z==0) ? g_qh : (z==1) ? g_kh : g_vh;
    bf16* outl = (z==0) ? g_ql : (z==1) ? g_kl : g_vl;
    const int mode = qkv ? ((z==2) ? 0 : 1) : 2;
#pragma unroll
    for (int mi=0; mi<4; mi++)
#pragma unroll
    for (int ni=0; ni<4; ni++){
        const int r0 = bm+wm+mi*16+g;
        const int c  = bn+wn+ni*8+tg*2;
        const float2 bv = *reinterpret_cast<const float2*>(&bias[c]);
        const float x0=acc[mi][ni][0]+bv.x, x1=acc[mi][ni][1]+bv.y;
        const float x2=acc[mi][ni][2]+bv.x, x3=acc[mi][ni][3]+bv.y;
        if (mode == 2){
            const float2 q0 = *reinterpret_cast<const float2*>(&resid[(size_t)r0*Dq + c]);
            const float2 q1 = *reinterpret_cast<const float2*>(&resid[(size_t)(r0+8)*Dq + c]);
            *reinterpret_cast<float2*>(&outf[(size_t)r0*Dq+c])     = make_float2(x0+q0.x, x1+q0.y);
            *reinterpret_cast<float2*>(&outf[(size_t)(r0+8)*Dq+c]) = make_float2(x2+q1.x, x3+q1.y);
        } else if (mode == 1){
            bf16 h0,l0,h1,l1;
#pragma unroll
            for (int hh = 0; hh < 2; hh++){
                const int rr = r0 + hh*8;
                const size_t tb = ((size_t)(rr>>7)*16 + (c>>6)) * 16384;
                const uint32_t off = SWZ(((rr&127)<<7) + ((c&63)<<1));
                const float y0 = hh ? x2 : x0;
                const float y1 = hh ? x3 : x1;
                split2(y0,h0,l0); split2(y1,h1,l1);
                *reinterpret_cast<bf162*>((char*)outh + tb + off) = __halves2bfloat162(h0,h1);
                *reinterpret_cast<bf162*>((char*)outl + tb + off) = __halves2bfloat162(l0,l1);
            }
        } else {
            bf16 h0,l0,h1,l1;
            split2(x0,h0,l0); split2(x1,h1,l1);
            *reinterpret_cast<bf162*>(&outh[(size_t)r0*Dq+c]) = __halves2bfloat162(h0,h1);
            *reinterpret_cast<bf162*>(&outl[(size_t)r0*Dq+c]) = __halves2bfloat162(l0,l1);
            split2(x2,h0,l0); split2(x3,h1,l1);
            *reinterpret_cast<bf162*>(&outh[(size_t)(r0+8)*Dq+c]) = __halves2bfloat162(h0,h1);
            *reinterpret_cast<bf162*>(&outl[(size_t)(r0+8)*Dq+c]) = __halves2bfloat162(l0,l1);
        }
    }
}

// ============================================================
// Scores: E -> g_e (HALF) via streaming stores + partial row sums
// ============================================================
#define SC_SMEM (128 + 65536)

__global__ __launch_bounds__(256) void scores_kernel(__half* __restrict__ escr)
{
    extern __shared__ __align__(128) char sm_[];
    const int bh = blockIdx.z, b = bh>>4, h = bh&15;
    const int tid = threadIdx.x, lane = tid&31, warp = tid>>5;
    const int bm = blockIdx.y*128, bn = blockIdx.x*128;
    const uint32_t sb = s2u(sm_);
    const uint32_t dat = sb + 128;

    const size_t atile = ((size_t)(b*16 + blockIdx.y)*16 + h) * 16384;
    const size_t btile = ((size_t)(b*16 + blockIdx.x)*16 + h) * 16384;

    if (tid == 0){
        mbar_init(sb, 1);
    }
    __syncthreads();
    if (tid == 0){
        mbar_expect(sb, 65536);
        bulk_ld(dat,        (const char*)g_qh + atile, 16384, sb);
        bulk_ld(dat+16384,  (const char*)g_ql + atile, 16384, sb);
        bulk_ld(dat+32768,  (const char*)g_kh + btile, 16384, sb);
        bulk_ld(dat+49152,  (const char*)g_kl + btile, 16384, sb);
    }

    const int wm = (warp>>2)*64, wn = (warp&3)*32;
    float acc[4][4][4] = {};

    mbar_wait(sb, 0);

#pragma unroll
    for (int ks = 0; ks < 4; ks++){
        uint32_t bhf[4][2], blf[4][2];
#pragma unroll
        for (int p = 0; p < 2; p++){
            const uint32_t roff = (uint32_t)(wn + p*16 + (lane&7) + ((lane>>4)&1)*8)*128
                                  + ks*32 + ((lane>>3)&1)*16;
            ldm4(dat + 32768 + SWZ(roff), bhf[2*p][0], bhf[2*p][1], bhf[2*p+1][0], bhf[2*p+1][1]);
            ldm4(dat + 49152 + SWZ(roff), blf[2*p][0], blf[2*p][1], blf[2*p+1][0], blf[2*p+1][1]);
        }
#pragma unroll
        for (int mi = 0; mi < 4; mi++){
            const uint32_t roff = (uint32_t)(wm + mi*16 + (lane&15))*128
                                  + ks*32 + ((lane>>4)&1)*16;
            uint32_t a0,a1,a2,a3, l0,l1,l2,l3;
            ldm4(dat +         SWZ(roff), a0,a1,a2,a3);
            ldm4(dat + 16384 + SWZ(roff), l0,l1,l2,l3);
#pragma unroll
            for (int ni = 0; ni < 4; ni++){
                mma16(acc[mi][ni], a0,a1,a2,a3, bhf[ni][0], bhf[ni][1]);
                mma16(acc[mi][ni], a0,a1,a2,a3, blf[ni][0], blf[ni][1]);
                mma16(acc[mi][ni], l0,l1,l2,l3, bhf[ni][0], bhf[ni][1]);
            }
        }
    }

    __shared__ float psum[128][4];
    __half* C = escr + (size_t)bh*Sq*Sq;
    const int g=lane>>2, tg=lane&3;
    const int wnidx = warp & 3;
#pragma unroll
    for (int mi=0; mi<4; mi++){
        float s0 = 0.f, s1 = 0.f;
#pragma unroll
        for (int ni=0; ni<4; ni++){
            const int r0 = bm+wm+mi*16+g;
            const int c  = bn+wn+ni*8+tg*2;
            const float e0 = __expf(acc[mi][ni][0]*0.125f);
            const float e1 = __expf(acc[mi][ni][1]*0.125f);
            const float e2 = __expf(acc[mi][ni][2]*0.125f);
            const float e3 = __expf(acc[mi][ni][3]*0.125f);
            stcsh2(&C[(size_t)r0*Sq+c],     __floats2half2_rn(e0, e1));
            stcsh2(&C[(size_t)(r0+8)*Sq+c], __floats2half2_rn(e2, e3));
            s0 += e0 + e1;
            s1 += e2 + e3;
        }
        s0 += __shfl_xor_sync(0xffffffffu, s0, 1);
        s0 += __shfl_xor_sync(0xffffffffu, s0, 2);
        s1 += __shfl_xor_sync(0xffffffffu, s1, 1);
        s1 += __shfl_xor_sync(0xffffffffu, s1, 2);
        if (tg == 0){
            psum[wm+mi*16+g][wnidx]   = s0;
            psum[wm+mi*16+g+8][wnidx] = s1;
        }
    }
    __syncthreads();
    if (tid < 128){
        const float t = psum[tid][0] + psum[tid][1] + psum[tid][2] + psum[tid][3];
        g_psum[((size_t)bh*16 + blockIdx.x)*Sq + bm + tid] = t;
    }
}

// ============================================================
// av (R14 structure, E half): 64-row q tiles, 5-stage ring, wait_group 3,
// fill-before-split, streaming P stores.
// stage: E half 64x32 (4096B, contiguous) | Vh 32x64 p144 (4608) | Vl (4608)
// ============================================================
#define AV_PSTG  4096
#define AV_VSTG  (32*144)
#define AV_STG   (AV_PSTG + 2*AV_VSTG)    // 13312
#define AV_NST   5
#define AV_EP    80
#define AV_EH    (64*AV_EP)
#define AV_SMEM  (512 + AV_NST*AV_STG + 2*AV_EH)   // 77312

__global__ __launch_bounds__(256,2) void av_kernel(const __half* __restrict__ escr,
                                                   float* __restrict__ scores)
{
    extern __shared__ __align__(128) char sm_[];
    const int qt = blockIdx.x, bh = blockIdx.y, b = bh>>4, h = bh&15;
    const int bm = qt*64;
    const int tid = threadIdx.x, lane = tid&31, warp = tid>>5;
    const __half* E = escr + (size_t)bh*Sq*Sq;
    float* P = scores + (size_t)bh*Sq*Sq;
    const bf16* Vhg = g_vh + (size_t)b*Sq*Dq + h*DHq;
    const bf16* Vlg = g_vl + (size_t)b*Sq*Dq + h*DHq;

    float* invs = reinterpret_cast<float*>(sm_);
    const uint32_t su = s2u(sm_ + 512);
    const uint32_t eu = su + AV_NST*AV_STG;

    if (tid < 64){
        float s = 0.f;
#pragma unroll
        for (int t = 0; t < 16; t++)
            s += g_psum[((size_t)bh*16 + t)*Sq + bm + tid];
        invs[tid] = 1.0f / s;
    }

    auto fill = [&](int p, int kt){
        const int k0 = kt*32;
        const uint32_t sbase = su + (uint32_t)p*AV_STG;
        {   // E: 256 chunks of 16B (8 halves) — one per thread
            const int rr = tid >> 2, cc = tid & 3;
            cpa16(sbase + (uint32_t)(tid*16),
                  &E[(size_t)(bm + rr)*Sq + k0 + cc*8]);
        }
#pragma unroll
        for (int c = 0; c < 2; c++){
            const int ch = tid + c*256;
            const int part = ch >> 8, idx = ch & 255;
            const int vr = idx >> 3, vc = idx & 7;
            const bf16* src = part ? Vlg : Vhg;
            cpa16(sbase + AV_PSTG + (uint32_t)(part*AV_VSTG + vr*144 + vc*16),
                  src + (size_t)(k0 + vr)*Dq + vc*8);
        }
        cpcommit();
    };

    fill(0,0); fill(1,1); fill(2,2); fill(3,3);
    __syncthreads();

    const int pr = tid>>2, pc0 = (tid&3)*8;
    const float inv = invs[pr];
    const int wm = (warp>>1)*16, wn = (warp&1)*32;

    float acc[4][4] = {};

    for (int kt = 0; kt < 64; kt++){
        const int s = kt % AV_NST;
        asm volatile("cp.async.wait_group 3;\n" ::: "memory");
        __syncthreads();

        if (kt+4 < 64) fill((kt+4)%AV_NST, kt+4);

        // normalize + STG P + split to E-smem
        {
            const char* ps = sm_ + 512 + s*AV_STG;
            char* EhB = sm_ + 512 + AV_NST*AV_STG;
            // read 8 halves (16B) for this thread's row/cols
            const uint4 raw = *reinterpret_cast<const uint4*>(ps + pr*64 + pc0*2);
            const __half2* hp = reinterpret_cast<const __half2*>(&raw);
#pragma unroll
            for (int j = 0; j < 2; j++){
                const int c = pc0 + j*4;
                const float2 f0 = __half22float2(hp[j*2+0]);
                const float2 f1 = __half22float2(hp[j*2+1]);
                float4 v = make_float4(f0.x*inv, f0.y*inv, f1.x*inv, f1.y*inv);
                stcs4(&P[(size_t)(bm + pr)*Sq + kt*32 + c], v);
                bf16 h0,l0,h1,l1,h2,l2,h3,l3;
                split2(v.x,h0,l0); split2(v.y,h1,l1); split2(v.z,h2,l2); split2(v.w,h3,l3);
                char* eh = EhB + pr*AV_EP + c*2;
                *reinterpret_cast<bf162*>(eh)           = __halves2bfloat162(h0,h1);
                *reinterpret_cast<bf162*>(eh+4)         = __halves2bfloat162(h2,h3);
                *reinterpret_cast<bf162*>(eh + AV_EH)   = __halves2bfloat162(l0,l1);
                *reinterpret_cast<bf162*>(eh + AV_EH+4) = __halves2bfloat162(l2,l3);
            }
        }
        __syncthreads();

        const uint32_t stv = su + (uint32_t)s*AV_STG + AV_PSTG;
#pragma unroll
        for (int ks = 0; ks < 2; ks++){
            uint32_t bhf[4][2], blf[4][2];
#pragma unroll
            for (int p = 0; p < 2; p++){
                const uint32_t ro = (uint32_t)((ks*16 + ((lane>>3)&1)*8 + (lane&7))*144
                                    + (wn + p*16 + ((lane>>4)&1)*8)*2);
                ldm4t(stv + ro,           bhf[2*p][0], bhf[2*p][1], bhf[2*p+1][0], bhf[2*p+1][1]);
                ldm4t(stv + AV_VSTG + ro, blf[2*p][0], blf[2*p][1], blf[2*p+1][0], blf[2*p+1][1]);
            }
            const uint32_t ao = (uint32_t)((wm + (lane&15))*AV_EP
                                + ks*32 + ((lane>>4)&1)*16);
            uint32_t a0,a1,a2,a3, l0,l1,l2,l3;
            ldm4(eu + ao,         a0,a1,a2,a3);
            ldm4(eu + AV_EH + ao, l0,l1,l2,l3);
#pragma unroll
            for (int ni = 0; ni < 4; ni++){
                mma16(acc[ni], a0,a1,a2,a3, bhf[ni][0], bhf[ni][1]);
                mma16(acc[ni], a0,a1,a2,a3, blf[ni][0], blf[ni][1]);
                mma16(acc[ni], l0,l1,l2,l3, bhf[ni][0], bhf[ni][1]);
            }
        }
    }

    const int g = lane>>2, tg = lane&3;
#pragma unroll
    for (int ni = 0; ni < 4; ni++){
        const int r0 = bm + wm + g;
        const int c  = wn + ni*8 + tg*2;
#pragma unroll
        for (int hh = 0; hh < 2; hh++){
            const int grow = b*Sq + r0 + hh*8;
            const size_t tb = ((size_t)((grow>>7)*16 + h)) * 16384;
            const uint32_t off = SWZ(((grow&127)<<7) + (c<<1));
            const float x0 = acc[ni][hh*2+0];
            const float x1 = acc[ni][hh*2+1];
            bf16 h0,l0,h1,l1;
            split2(x0,h0,l0); split2(x1,h1,l1);
            *reinterpret_cast<bf162*>((char*)g_pch + tb + off) = __halves2bfloat162(h0,h1);
            *reinterpret_cast<bf162*>((char*)g_pcl + tb + off) = __halves2bfloat162(l0,l1);
        }
    }
}

// ============================================================
// LayerNorm per row of g_y -> d_out
// ============================================================
__global__ void ln_kernel(const float* __restrict__ gamma,
                          const float* __restrict__ beta,
                          float* __restrict__ out)
{
    const size_t row = blockIdx.x;
    const float4* y = reinterpret_cast<const float4*>(g_y + row * (size_t)Dq);
    float4* o = reinterpret_cast<float4*>(out + row * (size_t)Dq);
    const int tid = threadIdx.x;
    __shared__ float sm[8], sm2[8];

    float4 v = y[tid];
    float s  = v.x + v.y + v.z + v.w;
    float s2 = v.x*v.x + v.y*v.y + v.z*v.z + v.w*v.w;
#pragma unroll
    for (int o2 = 16; o2 > 0; o2 >>= 1) {
        s  += __shfl_xor_sync(0xffffffffu, s,  o2);
        s2 += __shfl_xor_sync(0xffffffffu, s2, o2);
    }
    if ((tid & 31) == 0) { sm[tid>>5] = s; sm2[tid>>5] = s2; }
    __syncthreads();
    float ts = 0.f, ts2 = 0.f;
#pragma unroll
    for (int w = 0; w < 8; w++) { ts += sm[w]; ts2 += sm2[w]; }
    const float mean = ts * (1.0f/Dq);
    const float var  = ts2 * (1.0f/Dq) - mean*mean;
    const float rstd = rsqrtf(var + 1e-6f);

    const float4 gg = reinterpret_cast<const float4*>(gamma)[tid];
    const float4 bb = reinterpret_cast<const float4*>(beta)[tid];
    float4 r;
    r.x = (v.x - mean) * rstd * gg.x + bb.x;
    r.y = (v.y - mean) * rstd * gg.y + bb.y;
    r.z = (v.z - mean) * rstd * gg.z + bb.z;
    r.w = (v.w - mean) * rstd * gg.w + bb.w;
    o[tid] = r;
}

// ============================================================
extern "C" void kernel_launch(void* const* d_in, const int* in_sizes, int n_in,
                              void* d_out, int out_size)
{
    const float* Q     = (const float*)d_in[0];
    const float* K     = (const float*)d_in[1];
    const float* V     = (const float*)d_in[2];
    const float* Wq    = (const float*)d_in[3];
    const float* bq    = (const float*)d_in[4];
    const float* Wk    = (const float*)d_in[5];
    const float* bk    = (const float*)d_in[6];
    const float* Wv    = (const float*)d_in[7];
    const float* bv    = (const float*)d_in[8];
    const float* Wo    = (const float*)d_in[9];
    const float* bo    = (const float*)d_in[10];
    const float* gamma = (const float*)d_in[11];
    const float* beta  = (const float*)d_in[12];

    float* out    = (float*)d_out;
    float* scores = out + OUT_OFF;

    bf16 *pah, *pal, *pwh, *pwl, *pch, *pcl;
    float* gy;
    __half* ge;
    cudaGetSymbolAddress((void**)&pah,  g_pah);
    cudaGetSymbolAddress((void**)&pal,  g_pal);
    cudaGetSymbolAddress((void**)&pwh,  g_pwh);
    cudaGetSymbolAddress((void**)&pwl,  g_pwl);
    cudaGetSymbolAddress((void**)&pch,  g_pch);
    cudaGetSymbolAddress((void**)&pcl,  g_pcl);
    cudaGetSymbolAddress((void**)&gy,   g_y);
    cudaGetSymbolAddress((void**)&ge,   g_e);

    static bool attr_set = false;
    if (!attr_set){
        cudaFuncSetAttribute(proj_kernel,   cudaFuncAttributeMaxDynamicSharedMemorySize, PR_SMEM);
        cudaFuncSetAttribute(scores_kernel, cudaFuncAttributeMaxDynamicSharedMemorySize, SC_SMEM);
        cudaFuncSetAttribute(av_kernel,     cudaFuncAttributeMaxDynamicSharedMemorySize, AV_SMEM);
        attr_set = true;
    }

    dim3 blk(256);

    dim3 gSp(4096, 7);
    split_all<<<gSp, blk>>>(Q, K, V, Wq, Wk, Wv, Wo);

    dim3 gP3(8, 32, 3);
    proj_kernel<<<gP3, blk, PR_SMEM>>>(pah, pal, pwh, pwl,
                                       bq, bk, bv, nullptr, nullptr, 1);

    dim3 gSc(Sq/128, Sq/128, Bq*Hq);
    scores_kernel<<<gSc, blk, SC_SMEM>>>(ge);

    dim3 gAv(Sq/64, Bq*Hq);
    av_kernel<<<gAv, blk, AV_SMEM>>>(ge, scores);

    dim3 gP1(8, 32, 1);
    proj_kernel<<<gP1, blk, PR_SMEM>>>(pch, pcl, pwh + 3*(size_t)WN, pwl + 3*(size_t)WN,
                                       bo, bo, bo, Q, gy, 0);

    ln_kernel<<<(unsigned)Mq, blk>>>(gamma, beta, out);
}